// round 10
// baseline (speedup 1.0000x reference)
#include <cuda_runtime.h>
#include <cuda_bf16.h>
#include <math.h>

// ---------------------------------------------------------------------------
// POMO decoder v10 — HMMA split-bf16 3-pass, 32x32 warp tiles (LDSM:MMA 1:3).
// B=64, N=500, E=128, H=8, D=16
// ---------------------------------------------------------------------------

#define Bb 64
#define Nn 500
#define Hh 8
#define QKV_STRIDE 40

typedef unsigned long long ull;

__device__ unsigned g_maskbits[Bb * Nn * 16];
__device__ __nv_bfloat16 g_q_split[Bb * Hh * 512 * QKV_STRIDE];
__device__ __nv_bfloat16 g_k_split[Bb * Hh * 512 * QKV_STRIDE];
__device__ __nv_bfloat16 g_v_split[Bb * Hh * 512 * QKV_STRIDE];
__device__ __nv_bfloat16 g_enc_split[Bb * 512 * 256];
__device__ __nv_bfloat16 g_first_split[Bb * 512 * 256];
__device__ __nv_bfloat16 g_last_split[Bb * 512 * 256];
__device__ __nv_bfloat16 g_att_split[Bb * 512 * 256];
__device__ __nv_bfloat16 g_mh_split[Bb * 512 * 256];
__device__ __nv_bfloat16 g_w_split[5 * 128 * 256];

__device__ __forceinline__ unsigned smem_u32(const void* p) {
    unsigned a;
    asm("{ .reg .u64 t; cvta.to.shared.u64 t, %1; cvt.u32.u64 %0, t; }"
        : "=r"(a) : "l"(p));
    return a;
}

__device__ __forceinline__ void ldmx4(unsigned* r, unsigned addr) {
    asm volatile(
        "ldmatrix.sync.aligned.m8n8.x4.shared.b16 {%0,%1,%2,%3}, [%4];"
        : "=r"(r[0]), "=r"(r[1]), "=r"(r[2]), "=r"(r[3]) : "r"(addr));
}
__device__ __forceinline__ void ldmx4t(unsigned* r, unsigned addr) {
    asm volatile(
        "ldmatrix.sync.aligned.m8n8.x4.trans.shared.b16 {%0,%1,%2,%3}, [%4];"
        : "=r"(r[0]), "=r"(r[1]), "=r"(r[2]), "=r"(r[3]) : "r"(addr));
}
__device__ __forceinline__ void mma16816(float* c, const unsigned* a,
                                         unsigned b0, unsigned b1) {
    asm volatile(
        "mma.sync.aligned.m16n8k16.row.col.f32.bf16.bf16.f32 "
        "{%0,%1,%2,%3}, {%4,%5,%6,%7}, {%8,%9}, {%0,%1,%2,%3};"
        : "+f"(c[0]), "+f"(c[1]), "+f"(c[2]), "+f"(c[3])
        : "r"(a[0]), "r"(a[1]), "r"(a[2]), "r"(a[3]), "r"(b0), "r"(b1));
}
__device__ __forceinline__ unsigned pack_bf2(float x, float y) {
    __nv_bfloat162 h = __floats2bfloat162_rn(x, y);
    return *(unsigned*)&h;
}

// ---------------------------------------------------------------------------
// Prep (unchanged)
// ---------------------------------------------------------------------------
__global__ void __launch_bounds__(256)
prep_kernel(const float* __restrict__ enc_nodes,
            const float* __restrict__ enc_first,
            const float* __restrict__ enc_last,
            const float* __restrict__ mask,
            const float* __restrict__ Wqf, const float* __restrict__ Wql,
            const float* __restrict__ Wk, const float* __restrict__ Wv,
            const float* __restrict__ Wc) {
    int bi = blockIdx.x;
    int t = threadIdx.x;
    if (bi < 192) {
        int grp = bi >> 6, b = bi & 63;
        const float* src3 = (grp == 0) ? enc_nodes
                           : (grp == 1) ? enc_first : enc_last;
        __nv_bfloat16* dst3 = (grp == 0) ? g_enc_split
                             : (grp == 1) ? g_first_split : g_last_split;
        const float4* src = (const float4*)(src3 + (size_t)b * Nn * 128);
        for (int i4 = t; i4 < Nn * 32; i4 += 256) {
            int n = i4 >> 5, e4 = i4 & 31;
            float4 v = src[i4];
            __nv_bfloat162 h01 = __floats2bfloat162_rn(v.x, v.y);
            __nv_bfloat162 h23 = __floats2bfloat162_rn(v.z, v.w);
            float2 hf01 = __bfloat1622float2(h01);
            float2 hf23 = __bfloat1622float2(h23);
            __nv_bfloat162 l01 =
                __floats2bfloat162_rn(v.x - hf01.x, v.y - hf01.y);
            __nv_bfloat162 l23 =
                __floats2bfloat162_rn(v.z - hf23.x, v.w - hf23.y);
            __nv_bfloat16* dst = dst3 + ((size_t)(b * 512 + n)) * 256 + e4 * 4;
            *(__nv_bfloat162*)(dst) = h01;
            *(__nv_bfloat162*)(dst + 2) = h23;
            *(__nv_bfloat162*)(dst + 128) = l01;
            *(__nv_bfloat162*)(dst + 130) = l23;
        }
    } else if (bi < 197) {
        int widx = bi - 192;
        const float* W = (widx == 0) ? Wqf : (widx == 1) ? Wql
                        : (widx == 2) ? Wk : (widx == 3) ? Wv : Wc;
        __nv_bfloat16* dst = g_w_split + widx * 32768;
        for (int i = t; i < 16384; i += 256) {
            int f = i >> 7, e = i & 127;
            float r = W[i];
            __nv_bfloat16 hi = __float2bfloat16(r);
            float lo = r - __bfloat162float(hi);
            dst[f * 256 + e] = hi;
            dst[f * 256 + 128 + e] = __float2bfloat16(lo);
        }
    } else {
        int wid = t >> 5, lane = t & 31;
        int rowbase = (bi - 197) * 128 + wid * 16;
        for (int rr = 0; rr < 16; ++rr) {
            int row = rowbase + rr;
            const float* mrow = mask + (size_t)row * Nn;
            unsigned* brow = g_maskbits + (size_t)row * 16;
            #pragma unroll
            for (int w = 0; w < 16; ++w) {
                int g = w * 32 + lane;
                float v = (g < Nn) ? mrow[g] : -1e9f;
                unsigned bal = __ballot_sync(0xffffffffu, v > -1.0f);
                if (lane == 0) brow[w] = bal;
            }
        }
    }
}

// ---------------------------------------------------------------------------
// HMMA projection: 64 rows x 128 cols x K=128, 8 warps as 2 rowgrp x 4 colgrp,
// warp tile 32x32 (LDSM:MMA = 1:3, 8 independent acc chains).
// smem = (64+128)*264*2 = 101376 B -> 2 blocks/SM.
// ---------------------------------------------------------------------------
#define PRJ_SMEM ((64 + 128) * 264 * 2)

__device__ __forceinline__ void proj_body(
    const __nv_bfloat16* __restrict__ A0s, const __nv_bfloat16* __restrict__ W0s,
    const __nv_bfloat16* __restrict__ A1s, const __nv_bfloat16* __restrict__ W1s,
    const float* __restrict__ bias, __nv_bfloat16* __restrict__ outb,
    float scale, int mode, int m0) {
    extern __shared__ char smem[];
    __nv_bfloat16* As = (__nv_bfloat16*)smem;   // [64][264]
    __nv_bfloat16* Ws = As + 64 * 264;          // [128][264]

    const int t = threadIdx.x;
    const int w = t >> 5, lane = t & 31;
    const int wrow = (w & 1) * 32;
    const int wcol = (w >> 1) * 32;

    float acc[2][4][4];
    #pragma unroll
    for (int m = 0; m < 2; ++m)
        #pragma unroll
        for (int j = 0; j < 4; ++j)
            acc[m][j][0] = acc[m][j][1] = acc[m][j][2] = acc[m][j][3] = 0.f;

    const int npass = (A1s != nullptr) ? 2 : 1;
    for (int p = 0; p < npass; ++p) {
        const __nv_bfloat16* Ap = p ? A1s : A0s;
        const __nv_bfloat16* Wp = p ? W1s : W0s;
        if (p) __syncthreads();
        #pragma unroll
        for (int k = 0; k < 8; ++k) {
            int i4 = t + 256 * k;
            int row = i4 >> 5, c8 = i4 & 31;
            int m = m0 + row;
            int bb = m / Nn, nn = m - bb * Nn;
            uint4 v = *((const uint4*)(Ap + ((size_t)(bb * 512 + nn)) * 256) +
                        c8);
            *(uint4*)(As + row * 264 + c8 * 8) = v;
        }
        #pragma unroll
        for (int k = 0; k < 16; ++k) {
            int i4 = t + 256 * k;
            int row = i4 >> 5, c8 = i4 & 31;
            uint4 v = ((const uint4*)Wp)[i4];
            *(uint4*)(Ws + row * 264 + c8 * 8) = v;
        }
        __syncthreads();

        const unsigned arow = wrow + (lane & 15);
        const unsigned kcol = (lane >> 4) * 8;
        #pragma unroll
        for (int kk = 0; kk < 8; ++kk) {
            unsigned a0 = smem_u32(As + arow * 264 + kcol + kk * 16);
            unsigned a1 = smem_u32(As + (arow + 16) * 264 + kcol + kk * 16);
            unsigned ah0[4], al0[4], ah1[4], al1[4];
            ldmx4(ah0, a0); ldmx4(al0, a0 + 256);
            ldmx4(ah1, a1); ldmx4(al1, a1 + 256);
            #pragma unroll
            for (int n16 = 0; n16 < 2; ++n16) {
                unsigned ba = smem_u32(Ws + (wcol + n16 * 16 + (lane & 15)) *
                                                264 + kcol + kk * 16);
                unsigned bh[4], bl[4];
                ldmx4(bh, ba); ldmx4(bl, ba + 256);
                mma16816(acc[0][2 * n16],     ah0, bh[0], bh[2]);
                mma16816(acc[0][2 * n16 + 1], ah0, bh[1], bh[3]);
                mma16816(acc[1][2 * n16],     ah1, bh[0], bh[2]);
                mma16816(acc[1][2 * n16 + 1], ah1, bh[1], bh[3]);
                mma16816(acc[0][2 * n16],     ah0, bl[0], bl[2]);
                mma16816(acc[0][2 * n16 + 1], ah0, bl[1], bl[3]);
                mma16816(acc[1][2 * n16],     ah1, bl[0], bl[2]);
                mma16816(acc[1][2 * n16 + 1], ah1, bl[1], bl[3]);
                mma16816(acc[0][2 * n16],     al0, bh[0], bh[2]);
                mma16816(acc[0][2 * n16 + 1], al0, bh[1], bh[3]);
                mma16816(acc[1][2 * n16],     al1, bh[0], bh[2]);
                mma16816(acc[1][2 * n16 + 1], al1, bh[1], bh[3]);
            }
        }
    }

    #pragma unroll
    for (int m = 0; m < 2; ++m) {
        const int mr0 = m0 + wrow + m * 16 + (lane >> 2);
        const int mr1 = mr0 + 8;
        const int b0 = mr0 / Nn, n0v = mr0 - b0 * Nn;
        const int b1 = mr1 / Nn, n1v = mr1 - b1 * Nn;
        #pragma unroll
        for (int j = 0; j < 4; ++j) {
            int f = wcol + (j >> 1) * 16 + (j & 1) * 8 + (lane & 3) * 2;
            float bb0 = 0.f, bb1 = 0.f;
            if (bias) { bb0 = bias[f]; bb1 = bias[f + 1]; }
            float r00 = (acc[m][j][0] + bb0) * scale;
            float r01 = (acc[m][j][1] + bb1) * scale;
            float r10 = (acc[m][j][2] + bb0) * scale;
            float r11 = (acc[m][j][3] + bb1) * scale;
            __nv_bfloat162 h0 = __floats2bfloat162_rn(r00, r01);
            float2 ff0 = __bfloat1622float2(h0);
            unsigned lo0 = pack_bf2(r00 - ff0.x, r01 - ff0.y);
            __nv_bfloat162 h1 = __floats2bfloat162_rn(r10, r11);
            float2 ff1 = __bfloat1622float2(h1);
            unsigned lo1 = pack_bf2(r10 - ff1.x, r11 - ff1.y);
            if (mode == 0) {
                int h = f >> 4, d = f & 15;
                size_t base0 =
                    ((size_t)((b0 * Hh + h) * 512 + n0v)) * QKV_STRIDE + d;
                *(unsigned*)(outb + base0) = *(unsigned*)&h0;
                *(unsigned*)(outb + base0 + 16) = lo0;
                size_t base1 =
                    ((size_t)((b1 * Hh + h) * 512 + n1v)) * QKV_STRIDE + d;
                *(unsigned*)(outb + base1) = *(unsigned*)&h1;
                *(unsigned*)(outb + base1 + 16) = lo1;
            } else {
                size_t base0 = ((size_t)(b0 * 512 + n0v)) * 256 + f;
                *(unsigned*)(outb + base0) = *(unsigned*)&h0;
                *(unsigned*)(outb + base0 + 128) = lo0;
                size_t base1 = ((size_t)(b1 * 512 + n1v)) * 256 + f;
                *(unsigned*)(outb + base1) = *(unsigned*)&h1;
                *(unsigned*)(outb + base1 + 128) = lo1;
            }
        }
    }
}

__global__ void __launch_bounds__(256, 2)
qkv_mma_kernel() {
    const float QS = 1.4426950408889634f * 0.25f;
    int bi = blockIdx.x;
    int which = bi / 500;
    int m0 = (bi - which * 500) * 64;
    if (which == 0)
        proj_body(g_first_split, g_w_split, g_last_split,
                  g_w_split + 32768, nullptr, g_q_split, QS, 0, m0);
    else if (which == 1)
        proj_body(g_enc_split, g_w_split + 2 * 32768, nullptr, nullptr,
                  nullptr, g_k_split, 1.0f, 0, m0);
    else
        proj_body(g_enc_split, g_w_split + 3 * 32768, nullptr, nullptr,
                  nullptr, g_v_split, 1.0f, 0, m0);
}

__global__ void __launch_bounds__(256, 2)
combine_mma_kernel(const float* __restrict__ bc) {
    proj_body(g_att_split, g_w_split + 4 * 32768, nullptr, nullptr, bc,
              g_mh_split, 1.0f, 1, blockIdx.x * 64);
}

// ---------------------------------------------------------------------------
// Attention via HMMA (v9 form, passing)
// ---------------------------------------------------------------------------
#define ATT_SMEM ((128 + 512 + 512) * QKV_STRIDE * 2)

__global__ void __launch_bounds__(256, 2)
attn_mma_kernel() {
    extern __shared__ char smem[];
    __nv_bfloat16* Qs = (__nv_bfloat16*)smem;
    __nv_bfloat16* Ks = Qs + 128 * QKV_STRIDE;
    __nv_bfloat16* Vs = Ks + 512 * QKV_STRIDE;

    const int t = threadIdx.x;
    const int w = t >> 5, lane = t & 31;
    const int bi = blockIdx.x;
    const int bh = bi >> 2, qt = bi & 3;
    const int b = bh >> 3, h = bh & 7;
    const int q0 = qt * 128;

    {
        const uint4* qsrc =
            (const uint4*)(g_q_split + ((size_t)bh * 512 + q0) * QKV_STRIDE);
        #pragma unroll
        for (int k = 0; k < 3; ++k) {
            int i = t + 256 * k;
            if (i < 640) ((uint4*)Qs)[i] = qsrc[i];
        }
        const uint4* ksrc =
            (const uint4*)(g_k_split + (size_t)bh * 512 * QKV_STRIDE);
        #pragma unroll
        for (int k = 0; k < 10; ++k)
            ((uint4*)Ks)[t + 256 * k] = ksrc[t + 256 * k];
        const uint4* vsrc =
            (const uint4*)(g_v_split + (size_t)bh * 512 * QKV_STRIDE);
        #pragma unroll
        for (int k = 0; k < 10; ++k)
            ((uint4*)Vs)[t + 256 * k] = vsrc[t + 256 * k];
    }
    __syncthreads();

    unsigned aq_hi[4], aq_lo[4];
    {
        unsigned qaddr = smem_u32(Qs + (w * 16 + (lane & 15)) * QKV_STRIDE +
                                  (lane >> 4) * 8);
        ldmx4(aq_hi, qaddr);
        ldmx4(aq_lo, qaddr + 32);
    }

    float oacc[2][4];
    #pragma unroll
    for (int j = 0; j < 4; ++j) { oacc[0][j] = 0.f; oacc[1][j] = 0.f; }
    float rs0 = 0.f, rs1 = 0.f;

    const int nr0 = q0 + w * 16 + (lane >> 2);
    const int nr1 = nr0 + 8;
    const int nr0c = (nr0 < Nn) ? nr0 : 0;
    const int nr1c = (nr1 < Nn) ? nr1 : 0;

    for (int gt = 0; gt < 4; ++gt) {
        const int g0 = gt * 128;

        float sacc[16][4];
        #pragma unroll
        for (int i = 0; i < 16; ++i)
            sacc[i][0] = sacc[i][1] = sacc[i][2] = sacc[i][3] = 0.f;

        #pragma unroll
        for (int np = 0; np < 8; ++np) {
            unsigned ka = smem_u32(Ks + (g0 + np * 16 + (lane & 15)) *
                                            QKV_STRIDE +
                                   (lane >> 4) * 8);
            unsigned kh[4], kl[4];
            ldmx4(kh, ka);
            ldmx4(kl, ka + 32);
            mma16816(sacc[2 * np],     aq_hi, kh[0], kh[2]);
            mma16816(sacc[2 * np],     aq_hi, kl[0], kl[2]);
            mma16816(sacc[2 * np],     aq_lo, kh[0], kh[2]);
            mma16816(sacc[2 * np + 1], aq_hi, kh[1], kh[3]);
            mma16816(sacc[2 * np + 1], aq_hi, kl[1], kl[3]);
            mma16816(sacc[2 * np + 1], aq_lo, kh[1], kh[3]);
        }

        uint4 m0 = *(const uint4*)(g_maskbits + ((size_t)b * Nn + nr0c) * 16 +
                                   gt * 4);
        uint4 m1 = *(const uint4*)(g_maskbits + ((size_t)b * Nn + nr1c) * 16 +
                                   gt * 4);
        unsigned mw0[4] = {m0.x, m0.y, m0.z, m0.w};
        unsigned mw1[4] = {m1.x, m1.y, m1.z, m1.w};

        #pragma unroll
        for (int kk = 0; kk < 8; ++kk) {
            unsigned pf_hi[4], pf_lo[4];
            #pragma unroll
            for (int half = 0; half < 2; ++half) {
                int ntile = 2 * kk + half;
                unsigned w0 = mw0[ntile >> 2];
                unsigned w1 = mw1[ntile >> 2];
                int bitb = (ntile & 3) * 8 + (lane & 3) * 2;
                float p00 = exp2f(sacc[ntile][0]);
                float p01 = exp2f(sacc[ntile][1]);
                float p10 = exp2f(sacc[ntile][2]);
                float p11 = exp2f(sacc[ntile][3]);
                p00 = ((w0 >> bitb) & 1u) ? p00 : 0.f;
                p01 = ((w0 >> (bitb + 1)) & 1u) ? p01 : 0.f;
                p10 = ((w1 >> bitb) & 1u) ? p10 : 0.f;
                p11 = ((w1 >> (bitb + 1)) & 1u) ? p11 : 0.f;
                rs0 += p00 + p01;
                rs1 += p10 + p11;
                __nv_bfloat162 h0 = __floats2bfloat162_rn(p00, p01);
                __nv_bfloat162 h1 = __floats2bfloat162_rn(p10, p11);
                float2 hf0 = __bfloat1622float2(h0);
                float2 hf1 = __bfloat1622float2(h1);
                pf_hi[2 * half + 0] = *(unsigned*)&h0;
                pf_hi[2 * half + 1] = *(unsigned*)&h1;
                pf_lo[2 * half + 0] = pack_bf2(p00 - hf0.x, p01 - hf0.y);
                pf_lo[2 * half + 1] = pack_bf2(p10 - hf1.x, p11 - hf1.y);
            }
            unsigned va = smem_u32(Vs + (g0 + kk * 16 + (lane & 15)) *
                                            QKV_STRIDE +
                                   (lane >> 4) * 8);
            unsigned vh[4], vl[4];
            ldmx4t(vh, va);
            ldmx4t(vl, va + 32);
            mma16816(oacc[0], pf_hi, vh[0], vh[1]);
            mma16816(oacc[0], pf_hi, vl[0], vl[1]);
            mma16816(oacc[0], pf_lo, vh[0], vh[1]);
            mma16816(oacc[1], pf_hi, vh[2], vh[3]);
            mma16816(oacc[1], pf_hi, vl[2], vl[3]);
            mma16816(oacc[1], pf_lo, vh[2], vh[3]);
        }
    }

    rs0 += __shfl_xor_sync(0xffffffffu, rs0, 1);
    rs0 += __shfl_xor_sync(0xffffffffu, rs0, 2);
    rs1 += __shfl_xor_sync(0xffffffffu, rs1, 1);
    rs1 += __shfl_xor_sync(0xffffffffu, rs1, 2);
    float inv0 = __fdividef(1.0f, rs0);
    float inv1 = __fdividef(1.0f, rs1);

    const int d0 = (lane & 3) * 2;
    if (nr0 < Nn) {
        size_t base = ((size_t)(b * 512 + nr0)) * 256 + h * 16 + d0;
        float v0 = oacc[0][0] * inv0, v1 = oacc[0][1] * inv0;
        __nv_bfloat162 hh = __floats2bfloat162_rn(v0, v1);
        float2 hf = __bfloat1622float2(hh);
        *(unsigned*)(g_att_split + base) = *(unsigned*)&hh;
        *(unsigned*)(g_att_split + base + 128) =
            pack_bf2(v0 - hf.x, v1 - hf.y);
        v0 = oacc[1][0] * inv0; v1 = oacc[1][1] * inv0;
        hh = __floats2bfloat162_rn(v0, v1);
        hf = __bfloat1622float2(hh);
        *(unsigned*)(g_att_split + base + 8) = *(unsigned*)&hh;
        *(unsigned*)(g_att_split + base + 8 + 128) =
            pack_bf2(v0 - hf.x, v1 - hf.y);
    }
    if (nr1 < Nn) {
        size_t base = ((size_t)(b * 512 + nr1)) * 256 + h * 16 + d0;
        float v0 = oacc[0][2] * inv1, v1 = oacc[0][3] * inv1;
        __nv_bfloat162 hh = __floats2bfloat162_rn(v0, v1);
        float2 hf = __bfloat1622float2(hh);
        *(unsigned*)(g_att_split + base) = *(unsigned*)&hh;
        *(unsigned*)(g_att_split + base + 128) =
            pack_bf2(v0 - hf.x, v1 - hf.y);
        v0 = oacc[1][2] * inv1; v1 = oacc[1][3] * inv1;
        hh = __floats2bfloat162_rn(v0, v1);
        hf = __bfloat1622float2(hh);
        *(unsigned*)(g_att_split + base + 8) = *(unsigned*)&hh;
        *(unsigned*)(g_att_split + base + 8 + 128) =
            pack_bf2(v0 - hf.x, v1 - hf.y);
    }
}

// ---------------------------------------------------------------------------
// Pointer via HMMA v10 — 32x32 warp tiles; block = (b, 64-row tile),
// inner loop over 4 g-tiles of 128. 8 warps as 2 rowgrp x 4 colgrp.
// smem: As 64x264 + Bs 128x264 + rsum[4][64] = 102400 B -> 2 blocks/SM.
// ---------------------------------------------------------------------------
#define AS_STRIDE 264
#define PTR_SMEM ((64 + 128) * AS_STRIDE * 2 + 4 * 64 * 4)

__global__ void __launch_bounds__(256, 2)
pointer_mma_kernel(float* __restrict__ out) {
    extern __shared__ char smem[];
    __nv_bfloat16* As = (__nv_bfloat16*)smem;                 // [64][264]
    __nv_bfloat16* Bs = As + 64 * AS_STRIDE;                  // [128][264]
    float* rsum = (float*)(Bs + 128 * AS_STRIDE);             // [4][64]

    const int t = threadIdx.x;
    const int w = t >> 5, lane = t & 31;
    const int b = blockIdx.x >> 3;
    const int nt = blockIdx.x & 7;
    const int n0 = nt * 64;
    const int wrow = (w & 1) * 32;
    const int wcol = (w >> 1) * 32;
    const int colgrp = w >> 1;

    {
        const uint4* src =
            (const uint4*)(g_mh_split + ((size_t)(b * 512 + n0)) * 256);
        #pragma unroll
        for (int k = 0; k < 8; ++k) {
            int i4 = t + 256 * k;
            int row = i4 >> 5, c8 = i4 & 31;
            *(uint4*)(As + row * AS_STRIDE + c8 * 8) = src[i4];
        }
    }

    const float C1 = 0.08838834764831845f * 2.0f * 1.4426950408889634f;
    const float C2 = 10.0f * 1.4426950408889634f;

    // 4 per-thread rows: n0 + wrow + {0,8,16,24} + (lane>>2)
    int R[4], Rc[4];
    #pragma unroll
    for (int i = 0; i < 4; ++i) {
        R[i] = n0 + wrow + i * 8 + (lane >> 2);
        Rc[i] = (R[i] < Nn) ? R[i] : 0;
    }
    float rs[4] = {0.f, 0.f, 0.f, 0.f};

    const unsigned arow = wrow + (lane & 15);
    const unsigned kcol = (lane >> 4) * 8;

    for (int gt = 0; gt < 4; ++gt) {
        const int g0 = gt * 128;
        __syncthreads();
        {
            const uint4* src =
                (const uint4*)(g_enc_split + ((size_t)(b * 512 + g0)) * 256);
            #pragma unroll
            for (int k = 0; k < 16; ++k) {
                int i4 = t + 256 * k;
                int row = i4 >> 5, c8 = i4 & 31;
                *(uint4*)(Bs + row * AS_STRIDE + c8 * 8) = src[i4];
            }
        }
        __syncthreads();

        float acc[2][4][4];
        #pragma unroll
        for (int m = 0; m < 2; ++m)
            #pragma unroll
            for (int j = 0; j < 4; ++j)
                acc[m][j][0] = acc[m][j][1] = acc[m][j][2] = acc[m][j][3] = 0.f;

        #pragma unroll
        for (int kk = 0; kk < 8; ++kk) {
            unsigned a0 = smem_u32(As + arow * AS_STRIDE + kcol + kk * 16);
            unsigned a1 = smem_u32(As + (arow + 16) * AS_STRIDE + kcol +
                                   kk * 16);
            unsigned ah0[4], al0[4], ah1[4], al1[4];
            ldmx4(ah0, a0); ldmx4(al0, a0 + 256);
            ldmx4(ah1, a1); ldmx4(al1, a1 + 256);
            #pragma unroll
            for (int n16 = 0; n16 < 2; ++n16) {
                unsigned ba = smem_u32(Bs + (wcol + n16 * 16 + (lane & 15)) *
                                                AS_STRIDE + kcol + kk * 16);
                unsigned bh[4], bl[4];
                ldmx4(bh, ba); ldmx4(bl, ba + 256);
                mma16816(acc[0][2 * n16],     ah0, bh[0], bh[2]);
                mma16816(acc[0][2 * n16 + 1], ah0, bh[1], bh[3]);
                mma16816(acc[1][2 * n16],     ah1, bh[0], bh[2]);
                mma16816(acc[1][2 * n16 + 1], ah1, bh[1], bh[3]);
                mma16816(acc[0][2 * n16],     ah0, bl[0], bl[2]);
                mma16816(acc[0][2 * n16 + 1], ah0, bl[1], bl[3]);
                mma16816(acc[1][2 * n16],     ah1, bl[0], bl[2]);
                mma16816(acc[1][2 * n16 + 1], ah1, bl[1], bl[3]);
                mma16816(acc[0][2 * n16],     al0, bh[0], bh[2]);
                mma16816(acc[0][2 * n16 + 1], al0, bh[1], bh[3]);
                mma16816(acc[1][2 * n16],     al1, bh[0], bh[2]);
                mma16816(acc[1][2 * n16 + 1], al1, bh[1], bh[3]);
            }
        }

        // masks: one 32-bit word per row for this warp's 32-col group
        const int mword = gt * 4 + (wcol >> 5);
        unsigned mw[4];
        #pragma unroll
        for (int i = 0; i < 4; ++i)
            mw[i] = g_maskbits[((size_t)b * Nn + Rc[i]) * 16 + mword];

        #pragma unroll
        for (int m = 0; m < 2; ++m) {
            #pragma unroll
            for (int j = 0; j < 4; ++j) {
                int bitb = (j >> 1) * 16 + (j & 1) * 8 + (lane & 3) * 2;
                unsigned w0 = mw[2 * m];
                unsigned w1 = mw[2 * m + 1];
                float p00, p01, p10, p11;
                {
                    float u = exp2f(acc[m][j][0] * C1);
                    p00 = exp2f(C2 * (1.0f - __fdividef(2.0f, u + 1.0f)));
                }
                {
                    float u = exp2f(acc[m][j][1] * C1);
                    p01 = exp2f(C2 * (1.0f - __fdividef(2.0f, u + 1.0f)));
                }
                {
                    float u = exp2f(acc[m][j][2] * C1);
                    p10 = exp2f(C2 * (1.0f - __fdividef(2.0f, u + 1.0f)));
                }
                {
                    float u = exp2f(acc[m][j][3] * C1);
                    p11 = exp2f(C2 * (1.0f - __fdividef(2.0f, u + 1.0f)));
                }
                p00 = ((w0 >> bitb) & 1u) ? p00 : 0.f;
                p01 = ((w0 >> (bitb + 1)) & 1u) ? p01 : 0.f;
                p10 = ((w1 >> bitb) & 1u) ? p10 : 0.f;
                p11 = ((w1 >> (bitb + 1)) & 1u) ? p11 : 0.f;
                rs[2 * m] += p00 + p01;
                rs[2 * m + 1] += p10 + p11;
                int g = g0 + wcol + (j >> 1) * 16 + (j & 1) * 8 +
                        (lane & 3) * 2;
                if (g < Nn) {
                    if (R[2 * m] < Nn)
                        *(float2*)(out + ((size_t)b * Nn + R[2 * m]) * Nn +
                                   g) = make_float2(p00, p01);
                    if (R[2 * m + 1] < Nn)
                        *(float2*)(out + ((size_t)b * Nn + R[2 * m + 1]) * Nn +
                                   g) = make_float2(p10, p11);
                }
            }
        }
    }

    // quad-reduce rs, write per-colgrp slots
    #pragma unroll
    for (int i = 0; i < 4; ++i) {
        rs[i] += __shfl_xor_sync(0xffffffffu, rs[i], 1);
        rs[i] += __shfl_xor_sync(0xffffffffu, rs[i], 2);
    }
    if ((lane & 3) == 0) {
        #pragma unroll
        for (int i = 0; i < 4; ++i)
            rsum[colgrp * 64 + wrow + i * 8 + (lane >> 2)] = rs[i];
    }
    __syncthreads();

    for (int i4 = t; i4 < 64 * 125; i4 += 256) {
        int row = i4 / 125, c4 = i4 - row * 125;
        int n = n0 + row;
        if (n < Nn) {
            float inv = __fdividef(1.0f, rsum[row] + rsum[64 + row] +
                                          rsum[128 + row] + rsum[192 + row]);
            float4* po = (float4*)(out + ((size_t)b * Nn + n) * Nn) + c4;
            float4 p = *po;
            p.x *= inv; p.y *= inv; p.z *= inv; p.w *= inv;
            *po = p;
        }
    }
}

// ---------------------------------------------------------------------------
// Launch
// ---------------------------------------------------------------------------
extern "C" void kernel_launch(void* const* d_in, const int* in_sizes, int n_in,
                              void* d_out, int out_size) {
    const float* enc_nodes = (const float*)d_in[0];
    const float* enc_first = (const float*)d_in[1];
    const float* enc_last  = (const float*)d_in[2];
    const float* mask      = (const float*)d_in[3];
    const float* Wq_first  = (const float*)d_in[4];
    const float* Wq_last   = (const float*)d_in[5];
    const float* Wk        = (const float*)d_in[6];
    const float* Wv        = (const float*)d_in[7];
    const float* Wc        = (const float*)d_in[8];
    const float* bc        = (const float*)d_in[9];
    float* out = (float*)d_out;

    static int configured = 0;
    if (!configured) {
        cudaFuncSetAttribute(qkv_mma_kernel,
            cudaFuncAttributeMaxDynamicSharedMemorySize, PRJ_SMEM);
        cudaFuncSetAttribute(combine_mma_kernel,
            cudaFuncAttributeMaxDynamicSharedMemorySize, PRJ_SMEM);
        cudaFuncSetAttribute(attn_mma_kernel,
            cudaFuncAttributeMaxDynamicSharedMemorySize, ATT_SMEM);
        cudaFuncSetAttribute(pointer_mma_kernel,
            cudaFuncAttributeMaxDynamicSharedMemorySize, PTR_SMEM);
        configured = 1;
    }

    // 1) prep
    prep_kernel<<<447, 256>>>(enc_nodes, enc_first, enc_last, mask,
                              Wq_first, Wq_last, Wk, Wv, Wc);
    // 2) q/k/v projections (64x128 tiles, 32x32 warp tiles)
    qkv_mma_kernel<<<1500, 256, PRJ_SMEM>>>();
    // 3) attention
    attn_mma_kernel<<<Bb * Hh * 4, 256, ATT_SMEM>>>();
    // 4) combine
    combine_mma_kernel<<<500, 256, PRJ_SMEM>>>(bc);
    // 5) pointer
    pointer_mma_kernel<<<Bb * 8, 256, PTR_SMEM>>>(out);

    (void)in_sizes; (void)n_in; (void)out_size;
}

// round 11
// speedup vs baseline: 1.0116x; 1.0116x over previous
#include <cuda_runtime.h>
#include <cuda_bf16.h>
#include <math.h>

// ---------------------------------------------------------------------------
// POMO decoder v11 — v9 base (best: 297us) + attention restaged for 3/SM:
// K/V in 256-row halves (smem 50KB), 64-g score chunks (sacc 32 regs).
// B=64, N=500, E=128, H=8, D=16
// ---------------------------------------------------------------------------

#define Bb 64
#define Nn 500
#define Hh 8
#define QKV_STRIDE 40

typedef unsigned long long ull;

__device__ unsigned g_maskbits[Bb * Nn * 16];
__device__ __nv_bfloat16 g_q_split[Bb * Hh * 512 * QKV_STRIDE];
__device__ __nv_bfloat16 g_k_split[Bb * Hh * 512 * QKV_STRIDE];
__device__ __nv_bfloat16 g_v_split[Bb * Hh * 512 * QKV_STRIDE];
__device__ __nv_bfloat16 g_enc_split[Bb * 512 * 256];
__device__ __nv_bfloat16 g_first_split[Bb * 512 * 256];
__device__ __nv_bfloat16 g_last_split[Bb * 512 * 256];
__device__ __nv_bfloat16 g_att_split[Bb * 512 * 256];
__device__ __nv_bfloat16 g_mh_split[Bb * 512 * 256];
__device__ __nv_bfloat16 g_w_split[5 * 128 * 256];

__device__ __forceinline__ unsigned smem_u32(const void* p) {
    unsigned a;
    asm("{ .reg .u64 t; cvta.to.shared.u64 t, %1; cvt.u32.u64 %0, t; }"
        : "=r"(a) : "l"(p));
    return a;
}

__device__ __forceinline__ void ldmx4(unsigned* r, unsigned addr) {
    asm volatile(
        "ldmatrix.sync.aligned.m8n8.x4.shared.b16 {%0,%1,%2,%3}, [%4];"
        : "=r"(r[0]), "=r"(r[1]), "=r"(r[2]), "=r"(r[3]) : "r"(addr));
}
__device__ __forceinline__ void ldmx4t(unsigned* r, unsigned addr) {
    asm volatile(
        "ldmatrix.sync.aligned.m8n8.x4.trans.shared.b16 {%0,%1,%2,%3}, [%4];"
        : "=r"(r[0]), "=r"(r[1]), "=r"(r[2]), "=r"(r[3]) : "r"(addr));
}
__device__ __forceinline__ void mma16816(float* c, const unsigned* a,
                                         unsigned b0, unsigned b1) {
    asm volatile(
        "mma.sync.aligned.m16n8k16.row.col.f32.bf16.bf16.f32 "
        "{%0,%1,%2,%3}, {%4,%5,%6,%7}, {%8,%9}, {%0,%1,%2,%3};"
        : "+f"(c[0]), "+f"(c[1]), "+f"(c[2]), "+f"(c[3])
        : "r"(a[0]), "r"(a[1]), "r"(a[2]), "r"(a[3]), "r"(b0), "r"(b1));
}
__device__ __forceinline__ unsigned pack_bf2(float x, float y) {
    __nv_bfloat162 h = __floats2bfloat162_rn(x, y);
    return *(unsigned*)&h;
}

// ---------------------------------------------------------------------------
// Prep (unchanged from v9)
// ---------------------------------------------------------------------------
__global__ void __launch_bounds__(256)
prep_kernel(const float* __restrict__ enc_nodes,
            const float* __restrict__ enc_first,
            const float* __restrict__ enc_last,
            const float* __restrict__ mask,
            const float* __restrict__ Wqf, const float* __restrict__ Wql,
            const float* __restrict__ Wk, const float* __restrict__ Wv,
            const float* __restrict__ Wc) {
    int bi = blockIdx.x;
    int t = threadIdx.x;
    if (bi < 192) {
        int grp = bi >> 6, b = bi & 63;
        const float* src3 = (grp == 0) ? enc_nodes
                           : (grp == 1) ? enc_first : enc_last;
        __nv_bfloat16* dst3 = (grp == 0) ? g_enc_split
                             : (grp == 1) ? g_first_split : g_last_split;
        const float4* src = (const float4*)(src3 + (size_t)b * Nn * 128);
        for (int i4 = t; i4 < Nn * 32; i4 += 256) {
            int n = i4 >> 5, e4 = i4 & 31;
            float4 v = src[i4];
            __nv_bfloat162 h01 = __floats2bfloat162_rn(v.x, v.y);
            __nv_bfloat162 h23 = __floats2bfloat162_rn(v.z, v.w);
            float2 hf01 = __bfloat1622float2(h01);
            float2 hf23 = __bfloat1622float2(h23);
            __nv_bfloat162 l01 =
                __floats2bfloat162_rn(v.x - hf01.x, v.y - hf01.y);
            __nv_bfloat162 l23 =
                __floats2bfloat162_rn(v.z - hf23.x, v.w - hf23.y);
            __nv_bfloat16* dst = dst3 + ((size_t)(b * 512 + n)) * 256 + e4 * 4;
            *(__nv_bfloat162*)(dst) = h01;
            *(__nv_bfloat162*)(dst + 2) = h23;
            *(__nv_bfloat162*)(dst + 128) = l01;
            *(__nv_bfloat162*)(dst + 130) = l23;
        }
    } else if (bi < 197) {
        int widx = bi - 192;
        const float* W = (widx == 0) ? Wqf : (widx == 1) ? Wql
                        : (widx == 2) ? Wk : (widx == 3) ? Wv : Wc;
        __nv_bfloat16* dst = g_w_split + widx * 32768;
        for (int i = t; i < 16384; i += 256) {
            int f = i >> 7, e = i & 127;
            float r = W[i];
            __nv_bfloat16 hi = __float2bfloat16(r);
            float lo = r - __bfloat162float(hi);
            dst[f * 256 + e] = hi;
            dst[f * 256 + 128 + e] = __float2bfloat16(lo);
        }
    } else {
        int wid = t >> 5, lane = t & 31;
        int rowbase = (bi - 197) * 128 + wid * 16;
        for (int rr = 0; rr < 16; ++rr) {
            int row = rowbase + rr;
            const float* mrow = mask + (size_t)row * Nn;
            unsigned* brow = g_maskbits + (size_t)row * 16;
            #pragma unroll
            for (int w = 0; w < 16; ++w) {
                int g = w * 32 + lane;
                float v = (g < Nn) ? mrow[g] : -1e9f;
                unsigned bal = __ballot_sync(0xffffffffu, v > -1.0f);
                if (lane == 0) brow[w] = bal;
            }
        }
    }
}

// ---------------------------------------------------------------------------
// HMMA projection 64x64 tile body (v9, occ 3)
// ---------------------------------------------------------------------------
#define PRJ64_SMEM ((64 + 64) * 264 * 2)

__device__ __forceinline__ void proj64_body(
    const __nv_bfloat16* __restrict__ A0s, const __nv_bfloat16* __restrict__ W0s,
    const __nv_bfloat16* __restrict__ A1s, const __nv_bfloat16* __restrict__ W1s,
    const float* __restrict__ bias, __nv_bfloat16* __restrict__ outb,
    float scale, int mode, int m0, int f0) {
    extern __shared__ char smem[];
    __nv_bfloat16* As = (__nv_bfloat16*)smem;   // [64][264]
    __nv_bfloat16* Ws = As + 64 * 264;          // [64][264]

    const int t = threadIdx.x;
    const int w = t >> 5, lane = t & 31;
    const int wrow = (w & 3) * 16;
    const int whalf = w >> 2;

    float acc[4][4];
    #pragma unroll
    for (int i = 0; i < 4; ++i)
        acc[i][0] = acc[i][1] = acc[i][2] = acc[i][3] = 0.f;

    const int npass = (A1s != nullptr) ? 2 : 1;
    for (int p = 0; p < npass; ++p) {
        const __nv_bfloat16* Ap = p ? A1s : A0s;
        const __nv_bfloat16* Wp = p ? W1s : W0s;
        if (p) __syncthreads();
        #pragma unroll
        for (int k = 0; k < 8; ++k) {
            int i4 = t + 256 * k;
            int row = i4 >> 5, c8 = i4 & 31;
            int m = m0 + row;
            int bb = m / Nn, nn = m - bb * Nn;
            uint4 v = *((const uint4*)(Ap + ((size_t)(bb * 512 + nn)) * 256) +
                        c8);
            *(uint4*)(As + row * 264 + c8 * 8) = v;
        }
        #pragma unroll
        for (int k = 0; k < 8; ++k) {
            int i4 = t + 256 * k;
            int row = i4 >> 5, c8 = i4 & 31;
            uint4 v = *((const uint4*)(Wp + ((size_t)(f0 + row)) * 256) + c8);
            *(uint4*)(Ws + row * 264 + c8 * 8) = v;
        }
        __syncthreads();

        unsigned arowb = wrow + (lane & 15);
        unsigned acolb = (lane >> 4) * 8;
        unsigned browb = whalf * 32 + (lane & 15);
        #pragma unroll
        for (int kk = 0; kk < 8; ++kk) {
            unsigned aaddr = smem_u32(As + arowb * 264 + acolb + kk * 16);
            unsigned ah[4], al[4];
            ldmx4(ah, aaddr);
            ldmx4(al, aaddr + 128 * 2);
            #pragma unroll
            for (int np = 0; np < 2; ++np) {
                unsigned baddr = smem_u32(Ws + (np * 16 + browb) * 264 +
                                          acolb + kk * 16);
                unsigned bh[4], bl[4];
                ldmx4(bh, baddr);
                ldmx4(bl, baddr + 128 * 2);
                mma16816(acc[2 * np],     ah, bh[0], bh[2]);
                mma16816(acc[2 * np + 1], ah, bh[1], bh[3]);
                mma16816(acc[2 * np],     ah, bl[0], bl[2]);
                mma16816(acc[2 * np + 1], ah, bl[1], bl[3]);
                mma16816(acc[2 * np],     al, bh[0], bh[2]);
                mma16816(acc[2 * np + 1], al, bh[1], bh[3]);
            }
        }
        if (p + 1 < npass) __syncthreads();
    }

    const int mr0 = m0 + wrow + (lane >> 2);
    const int mr1 = mr0 + 8;
    const int b0 = mr0 / Nn, n0v = mr0 - b0 * Nn;
    const int b1 = mr1 / Nn, n1v = mr1 - b1 * Nn;
    #pragma unroll
    for (int ntile = 0; ntile < 4; ++ntile) {
        int f = f0 + whalf * 32 + ntile * 8 + (lane & 3) * 2;
        float bb0 = 0.f, bb1 = 0.f;
        if (bias) { bb0 = bias[f]; bb1 = bias[f + 1]; }
        float r00 = (acc[ntile][0] + bb0) * scale;
        float r01 = (acc[ntile][1] + bb1) * scale;
        float r10 = (acc[ntile][2] + bb0) * scale;
        float r11 = (acc[ntile][3] + bb1) * scale;
        __nv_bfloat162 h0 = __floats2bfloat162_rn(r00, r01);
        float2 ff0 = __bfloat1622float2(h0);
        unsigned lo0 = pack_bf2(r00 - ff0.x, r01 - ff0.y);
        __nv_bfloat162 h1 = __floats2bfloat162_rn(r10, r11);
        float2 ff1 = __bfloat1622float2(h1);
        unsigned lo1 = pack_bf2(r10 - ff1.x, r11 - ff1.y);
        if (mode == 0) {
            int h = f >> 4, d = f & 15;
            size_t base0 =
                ((size_t)((b0 * Hh + h) * 512 + n0v)) * QKV_STRIDE + d;
            *(unsigned*)(outb + base0) = *(unsigned*)&h0;
            *(unsigned*)(outb + base0 + 16) = lo0;
            size_t base1 =
                ((size_t)((b1 * Hh + h) * 512 + n1v)) * QKV_STRIDE + d;
            *(unsigned*)(outb + base1) = *(unsigned*)&h1;
            *(unsigned*)(outb + base1 + 16) = lo1;
        } else {
            size_t base0 = ((size_t)(b0 * 512 + n0v)) * 256 + f;
            *(unsigned*)(outb + base0) = *(unsigned*)&h0;
            *(unsigned*)(outb + base0 + 128) = lo0;
            size_t base1 = ((size_t)(b1 * 512 + n1v)) * 256 + f;
            *(unsigned*)(outb + base1) = *(unsigned*)&h1;
            *(unsigned*)(outb + base1 + 128) = lo1;
        }
    }
}

__global__ void __launch_bounds__(256, 3)
qkv_mma_kernel() {
    const float QS = 1.4426950408889634f * 0.25f;
    int bi = blockIdx.x;
    int which = bi / 1000;
    int rem = bi - which * 1000;
    int m0 = (rem >> 1) * 64;
    int f0 = (rem & 1) * 64;
    if (which == 0)
        proj64_body(g_first_split, g_w_split, g_last_split,
                    g_w_split + 32768, nullptr, g_q_split, QS, 0, m0, f0);
    else if (which == 1)
        proj64_body(g_enc_split, g_w_split + 2 * 32768, nullptr, nullptr,
                    nullptr, g_k_split, 1.0f, 0, m0, f0);
    else
        proj64_body(g_enc_split, g_w_split + 3 * 32768, nullptr, nullptr,
                    nullptr, g_v_split, 1.0f, 0, m0, f0);
}

__global__ void __launch_bounds__(256, 3)
combine_mma_kernel(const float* __restrict__ bc) {
    int bi = blockIdx.x;
    proj64_body(g_att_split, g_w_split + 4 * 32768, nullptr, nullptr, bc,
                g_mh_split, 1.0f, 1, (bi >> 1) * 64, (bi & 1) * 64);
}

// ---------------------------------------------------------------------------
// Attention v11: block = (b,h,qtile); K/V staged in 256-row halves,
// scores in 64-g chunks (sacc 32 regs). smem = (128+512)*80 = 51200 B.
// launch_bounds(256,3) -> 3 blocks/SM, 24 warps/SM.
// ---------------------------------------------------------------------------
#define ATT_SMEM ((128 + 256 + 256) * QKV_STRIDE * 2)

__global__ void __launch_bounds__(256, 3)
attn_mma_kernel() {
    extern __shared__ char smem[];
    __nv_bfloat16* Qs = (__nv_bfloat16*)smem;          // [128][40]
    __nv_bfloat16* Kh = Qs + 128 * QKV_STRIDE;         // [256][40]
    __nv_bfloat16* Vh = Kh + 256 * QKV_STRIDE;         // [256][40]

    const int t = threadIdx.x;
    const int w = t >> 5, lane = t & 31;
    const int bi = blockIdx.x;
    const int bh = bi >> 2, qt = bi & 3;
    const int b = bh >> 3, h = bh & 7;
    const int q0 = qt * 128;

    // load Q once
    {
        const uint4* qsrc =
            (const uint4*)(g_q_split + ((size_t)bh * 512 + q0) * QKV_STRIDE);
        #pragma unroll
        for (int k = 0; k < 3; ++k) {
            int i = t + 256 * k;
            if (i < 640) ((uint4*)Qs)[i] = qsrc[i];
        }
    }
    __syncthreads();

    unsigned aq_hi[4], aq_lo[4];
    {
        unsigned qaddr = smem_u32(Qs + (w * 16 + (lane & 15)) * QKV_STRIDE +
                                  (lane >> 4) * 8);
        ldmx4(aq_hi, qaddr);
        ldmx4(aq_lo, qaddr + 32);
    }

    float oacc[2][4];
    #pragma unroll
    for (int j = 0; j < 4; ++j) { oacc[0][j] = 0.f; oacc[1][j] = 0.f; }
    float rs0 = 0.f, rs1 = 0.f;

    const int nr0 = q0 + w * 16 + (lane >> 2);
    const int nr1 = nr0 + 8;
    const int nr0c = (nr0 < Nn) ? nr0 : 0;
    const int nr1c = (nr1 < Nn) ? nr1 : 0;

    for (int half = 0; half < 2; ++half) {
        __syncthreads();   // previous half's K/V reads done
        {
            const uint4* ksrc = (const uint4*)(g_k_split +
                ((size_t)bh * 512 + half * 256) * QKV_STRIDE);
            const uint4* vsrc = (const uint4*)(g_v_split +
                ((size_t)bh * 512 + half * 256) * QKV_STRIDE);
            #pragma unroll
            for (int k = 0; k < 5; ++k) {
                ((uint4*)Kh)[t + 256 * k] = ksrc[t + 256 * k];
                ((uint4*)Vh)[t + 256 * k] = vsrc[t + 256 * k];
            }
        }
        __syncthreads();

        for (int gt2 = 0; gt2 < 4; ++gt2) {
            const int lg0 = gt2 * 64;                       // local K/V row
            const int gw = half * 8 + gt2 * 2;              // mask word base

            float sacc[8][4];
            #pragma unroll
            for (int i = 0; i < 8; ++i)
                sacc[i][0] = sacc[i][1] = sacc[i][2] = sacc[i][3] = 0.f;

            #pragma unroll
            for (int np = 0; np < 4; ++np) {
                unsigned ka = smem_u32(Kh + (lg0 + np * 16 + (lane & 15)) *
                                                QKV_STRIDE + (lane >> 4) * 8);
                unsigned kh[4], kl[4];
                ldmx4(kh, ka);
                ldmx4(kl, ka + 32);
                mma16816(sacc[2 * np],     aq_hi, kh[0], kh[2]);
                mma16816(sacc[2 * np],     aq_hi, kl[0], kl[2]);
                mma16816(sacc[2 * np],     aq_lo, kh[0], kh[2]);
                mma16816(sacc[2 * np + 1], aq_hi, kh[1], kh[3]);
                mma16816(sacc[2 * np + 1], aq_hi, kl[1], kl[3]);
                mma16816(sacc[2 * np + 1], aq_lo, kh[1], kh[3]);
            }

            uint2 m0 = *(const uint2*)(g_maskbits +
                                       ((size_t)b * Nn + nr0c) * 16 + gw);
            uint2 m1 = *(const uint2*)(g_maskbits +
                                       ((size_t)b * Nn + nr1c) * 16 + gw);
            unsigned mw0[2] = {m0.x, m0.y};
            unsigned mw1[2] = {m1.x, m1.y};

            #pragma unroll
            for (int kk = 0; kk < 4; ++kk) {
                unsigned pf_hi[4], pf_lo[4];
                #pragma unroll
                for (int hf = 0; hf < 2; ++hf) {
                    int ntile = 2 * kk + hf;
                    unsigned w0 = mw0[ntile >> 2];
                    unsigned w1 = mw1[ntile >> 2];
                    int bitb = (ntile & 3) * 8 + (lane & 3) * 2;
                    float p00 = exp2f(sacc[ntile][0]);
                    float p01 = exp2f(sacc[ntile][1]);
                    float p10 = exp2f(sacc[ntile][2]);
                    float p11 = exp2f(sacc[ntile][3]);
                    p00 = ((w0 >> bitb) & 1u) ? p00 : 0.f;
                    p01 = ((w0 >> (bitb + 1)) & 1u) ? p01 : 0.f;
                    p10 = ((w1 >> bitb) & 1u) ? p10 : 0.f;
                    p11 = ((w1 >> (bitb + 1)) & 1u) ? p11 : 0.f;
                    rs0 += p00 + p01;
                    rs1 += p10 + p11;
                    __nv_bfloat162 h0 = __floats2bfloat162_rn(p00, p01);
                    __nv_bfloat162 h1 = __floats2bfloat162_rn(p10, p11);
                    float2 hf0 = __bfloat1622float2(h0);
                    float2 hf1 = __bfloat1622float2(h1);
                    pf_hi[2 * hf + 0] = *(unsigned*)&h0;
                    pf_hi[2 * hf + 1] = *(unsigned*)&h1;
                    pf_lo[2 * hf + 0] = pack_bf2(p00 - hf0.x, p01 - hf0.y);
                    pf_lo[2 * hf + 1] = pack_bf2(p10 - hf1.x, p11 - hf1.y);
                }
                unsigned va = smem_u32(Vh + (lg0 + kk * 16 + (lane & 15)) *
                                                QKV_STRIDE + (lane >> 4) * 8);
                unsigned vh[4], vl[4];
                ldmx4t(vh, va);
                ldmx4t(vl, va + 32);
                mma16816(oacc[0], pf_hi, vh[0], vh[1]);
                mma16816(oacc[0], pf_hi, vl[0], vl[1]);
                mma16816(oacc[0], pf_lo, vh[0], vh[1]);
                mma16816(oacc[1], pf_hi, vh[2], vh[3]);
                mma16816(oacc[1], pf_hi, vl[2], vl[3]);
                mma16816(oacc[1], pf_lo, vh[2], vh[3]);
            }
        }
    }

    rs0 += __shfl_xor_sync(0xffffffffu, rs0, 1);
    rs0 += __shfl_xor_sync(0xffffffffu, rs0, 2);
    rs1 += __shfl_xor_sync(0xffffffffu, rs1, 1);
    rs1 += __shfl_xor_sync(0xffffffffu, rs1, 2);
    float inv0 = __fdividef(1.0f, rs0);
    float inv1 = __fdividef(1.0f, rs1);

    const int d0 = (lane & 3) * 2;
    if (nr0 < Nn) {
        size_t base = ((size_t)(b * 512 + nr0)) * 256 + h * 16 + d0;
        float v0 = oacc[0][0] * inv0, v1 = oacc[0][1] * inv0;
        __nv_bfloat162 hh = __floats2bfloat162_rn(v0, v1);
        float2 hf = __bfloat1622float2(hh);
        *(unsigned*)(g_att_split + base) = *(unsigned*)&hh;
        *(unsigned*)(g_att_split + base + 128) =
            pack_bf2(v0 - hf.x, v1 - hf.y);
        v0 = oacc[1][0] * inv0; v1 = oacc[1][1] * inv0;
        hh = __floats2bfloat162_rn(v0, v1);
        hf = __bfloat1622float2(hh);
        *(unsigned*)(g_att_split + base + 8) = *(unsigned*)&hh;
        *(unsigned*)(g_att_split + base + 8 + 128) =
            pack_bf2(v0 - hf.x, v1 - hf.y);
    }
    if (nr1 < Nn) {
        size_t base = ((size_t)(b * 512 + nr1)) * 256 + h * 16 + d0;
        float v0 = oacc[0][2] * inv1, v1 = oacc[0][3] * inv1;
        __nv_bfloat162 hh = __floats2bfloat162_rn(v0, v1);
        float2 hf = __bfloat1622float2(hh);
        *(unsigned*)(g_att_split + base) = *(unsigned*)&hh;
        *(unsigned*)(g_att_split + base + 128) =
            pack_bf2(v0 - hf.x, v1 - hf.y);
        v0 = oacc[1][2] * inv1; v1 = oacc[1][3] * inv1;
        hh = __floats2bfloat162_rn(v0, v1);
        hf = __bfloat1622float2(hh);
        *(unsigned*)(g_att_split + base + 8) = *(unsigned*)&hh;
        *(unsigned*)(g_att_split + base + 8 + 128) =
            pack_bf2(v0 - hf.x, v1 - hf.y);
    }
}

// ---------------------------------------------------------------------------
// Pointer via HMMA (v9, occ 3)
// ---------------------------------------------------------------------------
#define AS_STRIDE 264
#define PTR_SMEM ((64 + 64) * AS_STRIDE * 2 + 512)

__global__ void __launch_bounds__(256, 3)
pointer_mma_kernel(float* __restrict__ out) {
    extern __shared__ char smem[];
    __nv_bfloat16* As = (__nv_bfloat16*)smem;                 // [64][264]
    __nv_bfloat16* Bs = As + 64 * AS_STRIDE;                  // [64][264]
    float* rsum = (float*)(Bs + 64 * AS_STRIDE);              // [2][64]

    const int t = threadIdx.x;
    const int w = t >> 5, lane = t & 31;
    const int b = blockIdx.x >> 3;
    const int nt = blockIdx.x & 7;
    const int n0 = nt * 64;
    const int wrow = (w & 3) * 16;
    const int whalf = w >> 2;

    {
        const uint4* src =
            (const uint4*)(g_mh_split + ((size_t)(b * 512 + n0)) * 256);
        #pragma unroll
        for (int k = 0; k < 8; ++k) {
            int i4 = t + 256 * k;
            int row = i4 >> 5, c8 = i4 & 31;
            *(uint4*)(As + row * AS_STRIDE + c8 * 8) = src[i4];
        }
    }

    const float C1 = 0.08838834764831845f * 2.0f * 1.4426950408889634f;
    const float C2 = 10.0f * 1.4426950408889634f;

    const int nr0 = n0 + wrow + (lane >> 2);
    const int nr1 = nr0 + 8;
    const int nr0c = (nr0 < Nn) ? nr0 : 0;
    const int nr1c = (nr1 < Nn) ? nr1 : 0;
    float rs0 = 0.f, rs1 = 0.f;

    unsigned arowb = wrow + (lane & 15);
    unsigned acolb = (lane >> 4) * 8;
    unsigned browb = whalf * 32 + (lane & 15);

    for (int gt = 0; gt < 8; ++gt) {
        const int g0 = gt * 64;
        __syncthreads();
        {
            const uint4* src =
                (const uint4*)(g_enc_split + ((size_t)(b * 512 + g0)) * 256);
            #pragma unroll
            for (int k = 0; k < 8; ++k) {
                int i4 = t + 256 * k;
                int row = i4 >> 5, c8 = i4 & 31;
                *(uint4*)(Bs + row * AS_STRIDE + c8 * 8) = src[i4];
            }
        }
        __syncthreads();

        float acc[4][4];
        #pragma unroll
        for (int i = 0; i < 4; ++i)
            acc[i][0] = acc[i][1] = acc[i][2] = acc[i][3] = 0.f;

        #pragma unroll
        for (int kk = 0; kk < 8; ++kk) {
            unsigned aaddr = smem_u32(As + arowb * AS_STRIDE + acolb + kk * 16);
            unsigned ah[4], al[4];
            ldmx4(ah, aaddr);
            ldmx4(al, aaddr + 128 * 2);
            #pragma unroll
            for (int np = 0; np < 2; ++np) {
                unsigned baddr = smem_u32(Bs + (np * 16 + browb) * AS_STRIDE +
                                          acolb + kk * 16);
                unsigned bh[4], bl[4];
                ldmx4(bh, baddr);
                ldmx4(bl, baddr + 128 * 2);
                mma16816(acc[2 * np],     ah, bh[0], bh[2]);
                mma16816(acc[2 * np + 1], ah, bh[1], bh[3]);
                mma16816(acc[2 * np],     ah, bl[0], bl[2]);
                mma16816(acc[2 * np + 1], ah, bl[1], bl[3]);
                mma16816(acc[2 * np],     al, bh[0], bh[2]);
                mma16816(acc[2 * np + 1], al, bh[1], bh[3]);
            }
        }

        int mword = gt * 2 + whalf;
        unsigned w0 = g_maskbits[((size_t)b * Nn + nr0c) * 16 + mword];
        unsigned w1 = g_maskbits[((size_t)b * Nn + nr1c) * 16 + mword];

        #pragma unroll
        for (int ntile = 0; ntile < 4; ++ntile) {
            int bitb = ntile * 8 + (lane & 3) * 2;
            float p00, p01, p10, p11;
            {
                float u = exp2f(acc[ntile][0] * C1);
                p00 = exp2f(C2 * (1.0f - __fdividef(2.0f, u + 1.0f)));
            }
            {
                float u = exp2f(acc[ntile][1] * C1);
                p01 = exp2f(C2 * (1.0f - __fdividef(2.0f, u + 1.0f)));
            }
            {
                float u = exp2f(acc[ntile][2] * C1);
                p10 = exp2f(C2 * (1.0f - __fdividef(2.0f, u + 1.0f)));
            }
            {
                float u = exp2f(acc[ntile][3] * C1);
                p11 = exp2f(C2 * (1.0f - __fdividef(2.0f, u + 1.0f)));
            }
            p00 = ((w0 >> bitb) & 1u) ? p00 : 0.f;
            p01 = ((w0 >> (bitb + 1)) & 1u) ? p01 : 0.f;
            p10 = ((w1 >> bitb) & 1u) ? p10 : 0.f;
            p11 = ((w1 >> (bitb + 1)) & 1u) ? p11 : 0.f;
            rs0 += p00 + p01;
            rs1 += p10 + p11;
            int g = g0 + whalf * 32 + ntile * 8 + (lane & 3) * 2;
            if (g < Nn) {
                if (nr0 < Nn)
                    *(float2*)(out + ((size_t)b * Nn + nr0) * Nn + g) =
                        make_float2(p00, p01);
                if (nr1 < Nn)
                    *(float2*)(out + ((size_t)b * Nn + nr1) * Nn + g) =
                        make_float2(p10, p11);
            }
        }
    }

    rs0 += __shfl_xor_sync(0xffffffffu, rs0, 1);
    rs0 += __shfl_xor_sync(0xffffffffu, rs0, 2);
    rs1 += __shfl_xor_sync(0xffffffffu, rs1, 1);
    rs1 += __shfl_xor_sync(0xffffffffu, rs1, 2);
    if ((lane & 3) == 0) {
        rsum[whalf * 64 + wrow + (lane >> 2)] = rs0;
        rsum[whalf * 64 + wrow + (lane >> 2) + 8] = rs1;
    }
    __syncthreads();

    for (int i4 = t; i4 < 64 * 125; i4 += 256) {
        int row = i4 / 125, c4 = i4 - row * 125;
        int n = n0 + row;
        if (n < Nn) {
            float inv = __fdividef(1.0f, rsum[row] + rsum[64 + row]);
            float4* po = (float4*)(out + ((size_t)b * Nn + n) * Nn) + c4;
            float4 p = *po;
            p.x *= inv; p.y *= inv; p.z *= inv; p.w *= inv;
            *po = p;
        }
    }
}

// ---------------------------------------------------------------------------
// Launch
// ---------------------------------------------------------------------------
extern "C" void kernel_launch(void* const* d_in, const int* in_sizes, int n_in,
                              void* d_out, int out_size) {
    const float* enc_nodes = (const float*)d_in[0];
    const float* enc_first = (const float*)d_in[1];
    const float* enc_last  = (const float*)d_in[2];
    const float* mask      = (const float*)d_in[3];
    const float* Wq_first  = (const float*)d_in[4];
    const float* Wq_last   = (const float*)d_in[5];
    const float* Wk        = (const float*)d_in[6];
    const float* Wv        = (const float*)d_in[7];
    const float* Wc        = (const float*)d_in[8];
    const float* bc        = (const float*)d_in[9];
    float* out = (float*)d_out;

    static int configured = 0;
    if (!configured) {
        cudaFuncSetAttribute(qkv_mma_kernel,
            cudaFuncAttributeMaxDynamicSharedMemorySize, PRJ64_SMEM);
        cudaFuncSetAttribute(combine_mma_kernel,
            cudaFuncAttributeMaxDynamicSharedMemorySize, PRJ64_SMEM);
        cudaFuncSetAttribute(attn_mma_kernel,
            cudaFuncAttributeMaxDynamicSharedMemorySize, ATT_SMEM);
        cudaFuncSetAttribute(pointer_mma_kernel,
            cudaFuncAttributeMaxDynamicSharedMemorySize, PTR_SMEM);
        configured = 1;
    }

    // 1) prep
    prep_kernel<<<447, 256>>>(enc_nodes, enc_first, enc_last, mask,
                              Wq_first, Wq_last, Wk, Wv, Wc);
    // 2) q/k/v projections (v9: 64x64 tiles, 3 blocks/SM)
    qkv_mma_kernel<<<3000, 256, PRJ64_SMEM>>>();
    // 3) attention (K/V halves, 3 blocks/SM)
    attn_mma_kernel<<<Bb * Hh * 4, 256, ATT_SMEM>>>();
    // 4) combine (v9)
    combine_mma_kernel<<<1000, 256, PRJ64_SMEM>>>(bc);
    // 5) pointer (v9)
    pointer_mma_kernel<<<Bb * 8, 256, PTR_SMEM>>>(out);

    (void)in_sizes; (void)n_in; (void)out_size;
}

// round 12
// speedup vs baseline: 1.0159x; 1.0042x over previous
#include <cuda_runtime.h>
#include <cuda_bf16.h>
#include <math.h>

// ---------------------------------------------------------------------------
// POMO decoder v12 — v9 GEMM cores; qkv/combine split operands inline from
// fp32 (kills prep splits + w_split round-trip); prep merged into launch 1.
// B=64, N=500, E=128, H=8, D=16
// ---------------------------------------------------------------------------

#define Bb 64
#define Nn 500
#define Hh 8
#define QKV_STRIDE 40

typedef unsigned long long ull;

__device__ unsigned g_maskbits[Bb * Nn * 16];
__device__ __nv_bfloat16 g_q_split[Bb * Hh * 512 * QKV_STRIDE];
__device__ __nv_bfloat16 g_k_split[Bb * Hh * 512 * QKV_STRIDE];
__device__ __nv_bfloat16 g_v_split[Bb * Hh * 512 * QKV_STRIDE];
__device__ __nv_bfloat16 g_enc_split[Bb * 512 * 256];
__device__ __nv_bfloat16 g_att_split[Bb * 512 * 256];
__device__ __nv_bfloat16 g_mh_split[Bb * 512 * 256];

__device__ __forceinline__ unsigned smem_u32(const void* p) {
    unsigned a;
    asm("{ .reg .u64 t; cvta.to.shared.u64 t, %1; cvt.u32.u64 %0, t; }"
        : "=r"(a) : "l"(p));
    return a;
}

__device__ __forceinline__ void ldmx4(unsigned* r, unsigned addr) {
    asm volatile(
        "ldmatrix.sync.aligned.m8n8.x4.shared.b16 {%0,%1,%2,%3}, [%4];"
        : "=r"(r[0]), "=r"(r[1]), "=r"(r[2]), "=r"(r[3]) : "r"(addr));
}
__device__ __forceinline__ void ldmx4t(unsigned* r, unsigned addr) {
    asm volatile(
        "ldmatrix.sync.aligned.m8n8.x4.trans.shared.b16 {%0,%1,%2,%3}, [%4];"
        : "=r"(r[0]), "=r"(r[1]), "=r"(r[2]), "=r"(r[3]) : "r"(addr));
}
__device__ __forceinline__ void mma16816(float* c, const unsigned* a,
                                         unsigned b0, unsigned b1) {
    asm volatile(
        "mma.sync.aligned.m16n8k16.row.col.f32.bf16.bf16.f32 "
        "{%0,%1,%2,%3}, {%4,%5,%6,%7}, {%8,%9}, {%0,%1,%2,%3};"
        : "+f"(c[0]), "+f"(c[1]), "+f"(c[2]), "+f"(c[3])
        : "r"(a[0]), "r"(a[1]), "r"(a[2]), "r"(a[3]), "r"(b0), "r"(b1));
}
__device__ __forceinline__ unsigned pack_bf2(float x, float y) {
    __nv_bfloat162 h = __floats2bfloat162_rn(x, y);
    return *(unsigned*)&h;
}

// split one float4 into hi/lo bf16x2 pairs and store at smem row layout
__device__ __forceinline__ void split_store(__nv_bfloat16* d, float4 v) {
    __nv_bfloat162 h01 = __floats2bfloat162_rn(v.x, v.y);
    __nv_bfloat162 h23 = __floats2bfloat162_rn(v.z, v.w);
    float2 f01 = __bfloat1622float2(h01);
    float2 f23 = __bfloat1622float2(h23);
    __nv_bfloat162 l01 = __floats2bfloat162_rn(v.x - f01.x, v.y - f01.y);
    __nv_bfloat162 l23 = __floats2bfloat162_rn(v.z - f23.x, v.w - f23.y);
    *(__nv_bfloat162*)(d) = h01;
    *(__nv_bfloat162*)(d + 2) = h23;
    *(__nv_bfloat162*)(d + 128) = l01;
    *(__nv_bfloat162*)(d + 130) = l23;
}

// ---------------------------------------------------------------------------
// HMMA 64x64 projection core (v9 schedule). A_FP32 selects A source:
//   true : A fp32 flat [32000][128], split inline
//   false: A bf16 split padded [b*512+n][256]
// W always fp32 [128][128], split inline. Output split bf16 (mode 0 heads /
// mode 1 mh). smem = 2*64*264*2 = 67584 B -> 3 blocks/SM.
// ---------------------------------------------------------------------------
#define PRJ64_SMEM ((64 + 64) * 264 * 2)

template <bool A_FP32>
__device__ __forceinline__ void proj64_body(
    const void* __restrict__ A0v, const float* __restrict__ W0,
    const void* __restrict__ A1v, const float* __restrict__ W1,
    const float* __restrict__ bias, __nv_bfloat16* __restrict__ outb,
    float scale, int mode, int m0, int f0) {
    extern __shared__ char smem[];
    __nv_bfloat16* As = (__nv_bfloat16*)smem;   // [64][264]
    __nv_bfloat16* Ws = As + 64 * 264;          // [64][264]

    const int t = threadIdx.x;
    const int w = t >> 5, lane = t & 31;
    const int wrow = (w & 3) * 16;
    const int whalf = w >> 2;

    float acc[4][4];
    #pragma unroll
    for (int i = 0; i < 4; ++i)
        acc[i][0] = acc[i][1] = acc[i][2] = acc[i][3] = 0.f;

    const int npass = (A1v != nullptr) ? 2 : 1;
    for (int p = 0; p < npass; ++p) {
        const void* Ap = p ? A1v : A0v;
        const float* Wp = p ? W1 : W0;
        if (p) __syncthreads();
        // A tile fill
        #pragma unroll
        for (int k = 0; k < 8; ++k) {
            int i4 = t + 256 * k;
            int row = i4 >> 5, e4 = i4 & 31;
            if (A_FP32) {
                float4 v = ((const float4*)Ap)[(size_t)(m0 + row) * 32 + e4];
                split_store(As + row * 264 + e4 * 4, v);
            } else {
                int m = m0 + row;
                int bb = m / Nn, nn = m - bb * Nn;
                uint4 v = *((const uint4*)((const __nv_bfloat16*)Ap +
                            ((size_t)(bb * 512 + nn)) * 256) + e4);
                *(uint4*)(As + row * 264 + e4 * 8) = v;
            }
        }
        // W tile fill (fp32 -> split)
        #pragma unroll
        for (int k = 0; k < 8; ++k) {
            int i4 = t + 256 * k;
            int row = i4 >> 5, e4 = i4 & 31;
            float4 v = ((const float4*)Wp)[(size_t)(f0 + row) * 32 + e4];
            split_store(Ws + row * 264 + e4 * 4, v);
        }
        __syncthreads();

        unsigned arowb = wrow + (lane & 15);
        unsigned acolb = (lane >> 4) * 8;
        unsigned browb = whalf * 32 + (lane & 15);
        #pragma unroll
        for (int kk = 0; kk < 8; ++kk) {
            unsigned aaddr = smem_u32(As + arowb * 264 + acolb + kk * 16);
            unsigned ah[4], al[4];
            ldmx4(ah, aaddr);
            ldmx4(al, aaddr + 128 * 2);
            #pragma unroll
            for (int np = 0; np < 2; ++np) {
                unsigned baddr = smem_u32(Ws + (np * 16 + browb) * 264 +
                                          acolb + kk * 16);
                unsigned bh[4], bl[4];
                ldmx4(bh, baddr);
                ldmx4(bl, baddr + 128 * 2);
                mma16816(acc[2 * np],     ah, bh[0], bh[2]);
                mma16816(acc[2 * np + 1], ah, bh[1], bh[3]);
                mma16816(acc[2 * np],     ah, bl[0], bl[2]);
                mma16816(acc[2 * np + 1], ah, bl[1], bl[3]);
                mma16816(acc[2 * np],     al, bh[0], bh[2]);
                mma16816(acc[2 * np + 1], al, bh[1], bh[3]);
            }
        }
        if (p + 1 < npass) __syncthreads();
    }

    const int mr0 = m0 + wrow + (lane >> 2);
    const int mr1 = mr0 + 8;
    const int b0 = mr0 / Nn, n0v = mr0 - b0 * Nn;
    const int b1 = mr1 / Nn, n1v = mr1 - b1 * Nn;
    #pragma unroll
    for (int ntile = 0; ntile < 4; ++ntile) {
        int f = f0 + whalf * 32 + ntile * 8 + (lane & 3) * 2;
        float bb0 = 0.f, bb1 = 0.f;
        if (bias) { bb0 = bias[f]; bb1 = bias[f + 1]; }
        float r00 = (acc[ntile][0] + bb0) * scale;
        float r01 = (acc[ntile][1] + bb1) * scale;
        float r10 = (acc[ntile][2] + bb0) * scale;
        float r11 = (acc[ntile][3] + bb1) * scale;
        __nv_bfloat162 h0 = __floats2bfloat162_rn(r00, r01);
        float2 ff0 = __bfloat1622float2(h0);
        unsigned lo0 = pack_bf2(r00 - ff0.x, r01 - ff0.y);
        __nv_bfloat162 h1 = __floats2bfloat162_rn(r10, r11);
        float2 ff1 = __bfloat1622float2(h1);
        unsigned lo1 = pack_bf2(r10 - ff1.x, r11 - ff1.y);
        if (mode == 0) {
            int h = f >> 4, d = f & 15;
            size_t base0 =
                ((size_t)((b0 * Hh + h) * 512 + n0v)) * QKV_STRIDE + d;
            *(unsigned*)(outb + base0) = *(unsigned*)&h0;
            *(unsigned*)(outb + base0 + 16) = lo0;
            size_t base1 =
                ((size_t)((b1 * Hh + h) * 512 + n1v)) * QKV_STRIDE + d;
            *(unsigned*)(outb + base1) = *(unsigned*)&h1;
            *(unsigned*)(outb + base1 + 16) = lo1;
        } else {
            size_t base0 = ((size_t)(b0 * 512 + n0v)) * 256 + f;
            *(unsigned*)(outb + base0) = *(unsigned*)&h0;
            *(unsigned*)(outb + base0 + 128) = lo0;
            size_t base1 = ((size_t)(b1 * 512 + n1v)) * 256 + f;
            *(unsigned*)(outb + base1) = *(unsigned*)&h1;
            *(unsigned*)(outb + base1 + 128) = lo1;
        }
    }
}

// ---------------------------------------------------------------------------
// Launch 1: qkv projections (inline fp32 splits) + enc split + maskbits.
// grid = 3000 (qkv) + 64 (enc split) + 250 (maskbits) = 3314.
// ---------------------------------------------------------------------------
__global__ void __launch_bounds__(256, 3)
qkv_prep_kernel(const float* __restrict__ enc_nodes,
                const float* __restrict__ enc_first,
                const float* __restrict__ enc_last,
                const float* __restrict__ mask,
                const float* __restrict__ Wqf, const float* __restrict__ Wql,
                const float* __restrict__ Wk, const float* __restrict__ Wv) {
    int bi = blockIdx.x;
    if (bi < 3000) {
        const float QS = 1.4426950408889634f * 0.25f;  // log2e / sqrt(D)
        int which = bi / 1000;
        int rem = bi - which * 1000;
        int m0 = (rem >> 1) * 64;
        int f0 = (rem & 1) * 64;
        if (which == 0)
            proj64_body<true>(enc_first, Wqf, enc_last, Wql, nullptr,
                              g_q_split, QS, 0, m0, f0);
        else if (which == 1)
            proj64_body<true>(enc_nodes, Wk, nullptr, nullptr, nullptr,
                              g_k_split, 1.0f, 0, m0, f0);
        else
            proj64_body<true>(enc_nodes, Wv, nullptr, nullptr, nullptr,
                              g_v_split, 1.0f, 0, m0, f0);
    } else if (bi < 3064) {
        // enc split (for pointer B operand): one batch per block
        int b = bi - 3000;
        int t = threadIdx.x;
        const float4* src = (const float4*)(enc_nodes + (size_t)b * Nn * 128);
        for (int i4 = t; i4 < Nn * 32; i4 += 256) {
            int n = i4 >> 5, e4 = i4 & 31;
            split_store(g_enc_split + ((size_t)(b * 512 + n)) * 256 + e4 * 4,
                        src[i4]);
        }
    } else {
        // maskbits: 128 rows per block (250 blocks)
        int t = threadIdx.x;
        int wid = t >> 5, lane = t & 31;
        int rowbase = (bi - 3064) * 128 + wid * 16;
        for (int rr = 0; rr < 16; ++rr) {
            int row = rowbase + rr;
            const float* mrow = mask + (size_t)row * Nn;
            unsigned* brow = g_maskbits + (size_t)row * 16;
            #pragma unroll
            for (int w = 0; w < 16; ++w) {
                int g = w * 32 + lane;
                float v = (g < Nn) ? mrow[g] : -1e9f;
                unsigned bal = __ballot_sync(0xffffffffu, v > -1.0f);
                if (lane == 0) brow[w] = bal;
            }
        }
    }
}

// ---------------------------------------------------------------------------
// Launch 3: combine (A = att_split bf16, W = Wc fp32 inline split)
// ---------------------------------------------------------------------------
__global__ void __launch_bounds__(256, 3)
combine_mma_kernel(const float* __restrict__ Wc, const float* __restrict__ bc) {
    int bi = blockIdx.x;
    proj64_body<false>(g_att_split, Wc, nullptr, nullptr, bc,
                       g_mh_split, 1.0f, 1, (bi >> 1) * 64, (bi & 1) * 64);
}

// ---------------------------------------------------------------------------
// Launch 2: attention via HMMA (v9/v7 form — best measured)
// ---------------------------------------------------------------------------
#define ATT_SMEM ((128 + 512 + 512) * QKV_STRIDE * 2)

__global__ void __launch_bounds__(256, 2)
attn_mma_kernel() {
    extern __shared__ char smem[];
    __nv_bfloat16* Qs = (__nv_bfloat16*)smem;
    __nv_bfloat16* Ks = Qs + 128 * QKV_STRIDE;
    __nv_bfloat16* Vs = Ks + 512 * QKV_STRIDE;

    const int t = threadIdx.x;
    const int w = t >> 5, lane = t & 31;
    const int bi = blockIdx.x;
    const int bh = bi >> 2, qt = bi & 3;
    const int b = bh >> 3, h = bh & 7;
    const int q0 = qt * 128;

    {
        const uint4* qsrc =
            (const uint4*)(g_q_split + ((size_t)bh * 512 + q0) * QKV_STRIDE);
        #pragma unroll
        for (int k = 0; k < 3; ++k) {
            int i = t + 256 * k;
            if (i < 640) ((uint4*)Qs)[i] = qsrc[i];
        }
        const uint4* ksrc =
            (const uint4*)(g_k_split + (size_t)bh * 512 * QKV_STRIDE);
        #pragma unroll
        for (int k = 0; k < 10; ++k)
            ((uint4*)Ks)[t + 256 * k] = ksrc[t + 256 * k];
        const uint4* vsrc =
            (const uint4*)(g_v_split + (size_t)bh * 512 * QKV_STRIDE);
        #pragma unroll
        for (int k = 0; k < 10; ++k)
            ((uint4*)Vs)[t + 256 * k] = vsrc[t + 256 * k];
    }
    __syncthreads();

    unsigned aq_hi[4], aq_lo[4];
    {
        unsigned qaddr = smem_u32(Qs + (w * 16 + (lane & 15)) * QKV_STRIDE +
                                  (lane >> 4) * 8);
        ldmx4(aq_hi, qaddr);
        ldmx4(aq_lo, qaddr + 32);
    }

    float oacc[2][4];
    #pragma unroll
    for (int j = 0; j < 4; ++j) { oacc[0][j] = 0.f; oacc[1][j] = 0.f; }
    float rs0 = 0.f, rs1 = 0.f;

    const int nr0 = q0 + w * 16 + (lane >> 2);
    const int nr1 = nr0 + 8;
    const int nr0c = (nr0 < Nn) ? nr0 : 0;
    const int nr1c = (nr1 < Nn) ? nr1 : 0;

    for (int gt = 0; gt < 4; ++gt) {
        const int g0 = gt * 128;

        float sacc[16][4];
        #pragma unroll
        for (int i = 0; i < 16; ++i)
            sacc[i][0] = sacc[i][1] = sacc[i][2] = sacc[i][3] = 0.f;

        #pragma unroll
        for (int np = 0; np < 8; ++np) {
            unsigned ka = smem_u32(Ks + (g0 + np * 16 + (lane & 15)) *
                                            QKV_STRIDE +
                                   (lane >> 4) * 8);
            unsigned kh[4], kl[4];
            ldmx4(kh, ka);
            ldmx4(kl, ka + 32);
            mma16816(sacc[2 * np],     aq_hi, kh[0], kh[2]);
            mma16816(sacc[2 * np],     aq_hi, kl[0], kl[2]);
            mma16816(sacc[2 * np],     aq_lo, kh[0], kh[2]);
            mma16816(sacc[2 * np + 1], aq_hi, kh[1], kh[3]);
            mma16816(sacc[2 * np + 1], aq_hi, kl[1], kl[3]);
            mma16816(sacc[2 * np + 1], aq_lo, kh[1], kh[3]);
        }

        uint4 m0 = *(const uint4*)(g_maskbits + ((size_t)b * Nn + nr0c) * 16 +
                                   gt * 4);
        uint4 m1 = *(const uint4*)(g_maskbits + ((size_t)b * Nn + nr1c) * 16 +
                                   gt * 4);
        unsigned mw0[4] = {m0.x, m0.y, m0.z, m0.w};
        unsigned mw1[4] = {m1.x, m1.y, m1.z, m1.w};

        #pragma unroll
        for (int kk = 0; kk < 8; ++kk) {
            unsigned pf_hi[4], pf_lo[4];
            #pragma unroll
            for (int half = 0; half < 2; ++half) {
                int ntile = 2 * kk + half;
                unsigned w0 = mw0[ntile >> 2];
                unsigned w1 = mw1[ntile >> 2];
                int bitb = (ntile & 3) * 8 + (lane & 3) * 2;
                float p00 = exp2f(sacc[ntile][0]);
                float p01 = exp2f(sacc[ntile][1]);
                float p10 = exp2f(sacc[ntile][2]);
                float p11 = exp2f(sacc[ntile][3]);
                p00 = ((w0 >> bitb) & 1u) ? p00 : 0.f;
                p01 = ((w0 >> (bitb + 1)) & 1u) ? p01 : 0.f;
                p10 = ((w1 >> bitb) & 1u) ? p10 : 0.f;
                p11 = ((w1 >> (bitb + 1)) & 1u) ? p11 : 0.f;
                rs0 += p00 + p01;
                rs1 += p10 + p11;
                __nv_bfloat162 h0 = __floats2bfloat162_rn(p00, p01);
                __nv_bfloat162 h1 = __floats2bfloat162_rn(p10, p11);
                float2 hf0 = __bfloat1622float2(h0);
                float2 hf1 = __bfloat1622float2(h1);
                pf_hi[2 * half + 0] = *(unsigned*)&h0;
                pf_hi[2 * half + 1] = *(unsigned*)&h1;
                pf_lo[2 * half + 0] = pack_bf2(p00 - hf0.x, p01 - hf0.y);
                pf_lo[2 * half + 1] = pack_bf2(p10 - hf1.x, p11 - hf1.y);
            }
            unsigned va = smem_u32(Vs + (g0 + kk * 16 + (lane & 15)) *
                                            QKV_STRIDE +
                                   (lane >> 4) * 8);
            unsigned vh[4], vl[4];
            ldmx4t(vh, va);
            ldmx4t(vl, va + 32);
            mma16816(oacc[0], pf_hi, vh[0], vh[1]);
            mma16816(oacc[0], pf_hi, vl[0], vl[1]);
            mma16816(oacc[0], pf_lo, vh[0], vh[1]);
            mma16816(oacc[1], pf_hi, vh[2], vh[3]);
            mma16816(oacc[1], pf_hi, vl[2], vl[3]);
            mma16816(oacc[1], pf_lo, vh[2], vh[3]);
        }
    }

    rs0 += __shfl_xor_sync(0xffffffffu, rs0, 1);
    rs0 += __shfl_xor_sync(0xffffffffu, rs0, 2);
    rs1 += __shfl_xor_sync(0xffffffffu, rs1, 1);
    rs1 += __shfl_xor_sync(0xffffffffu, rs1, 2);
    float inv0 = __fdividef(1.0f, rs0);
    float inv1 = __fdividef(1.0f, rs1);

    const int d0 = (lane & 3) * 2;
    if (nr0 < Nn) {
        size_t base = ((size_t)(b * 512 + nr0)) * 256 + h * 16 + d0;
        float v0 = oacc[0][0] * inv0, v1 = oacc[0][1] * inv0;
        __nv_bfloat162 hh = __floats2bfloat162_rn(v0, v1);
        float2 hf = __bfloat1622float2(hh);
        *(unsigned*)(g_att_split + base) = *(unsigned*)&hh;
        *(unsigned*)(g_att_split + base + 128) =
            pack_bf2(v0 - hf.x, v1 - hf.y);
        v0 = oacc[1][0] * inv0; v1 = oacc[1][1] * inv0;
        hh = __floats2bfloat162_rn(v0, v1);
        hf = __bfloat1622float2(hh);
        *(unsigned*)(g_att_split + base + 8) = *(unsigned*)&hh;
        *(unsigned*)(g_att_split + base + 8 + 128) =
            pack_bf2(v0 - hf.x, v1 - hf.y);
    }
    if (nr1 < Nn) {
        size_t base = ((size_t)(b * 512 + nr1)) * 256 + h * 16 + d0;
        float v0 = oacc[0][2] * inv1, v1 = oacc[0][3] * inv1;
        __nv_bfloat162 hh = __floats2bfloat162_rn(v0, v1);
        float2 hf = __bfloat1622float2(hh);
        *(unsigned*)(g_att_split + base) = *(unsigned*)&hh;
        *(unsigned*)(g_att_split + base + 128) =
            pack_bf2(v0 - hf.x, v1 - hf.y);
        v0 = oacc[1][2] * inv1; v1 = oacc[1][3] * inv1;
        hh = __floats2bfloat162_rn(v0, v1);
        hf = __bfloat1622float2(hh);
        *(unsigned*)(g_att_split + base + 8) = *(unsigned*)&hh;
        *(unsigned*)(g_att_split + base + 8 + 128) =
            pack_bf2(v0 - hf.x, v1 - hf.y);
    }
}

// ---------------------------------------------------------------------------
// Launch 4: pointer via HMMA (v9, occ 3 — best measured)
// ---------------------------------------------------------------------------
#define AS_STRIDE 264
#define PTR_SMEM ((64 + 64) * AS_STRIDE * 2 + 512)

__global__ void __launch_bounds__(256, 3)
pointer_mma_kernel(float* __restrict__ out) {
    extern __shared__ char smem[];
    __nv_bfloat16* As = (__nv_bfloat16*)smem;                 // [64][264]
    __nv_bfloat16* Bs = As + 64 * AS_STRIDE;                  // [64][264]
    float* rsum = (float*)(Bs + 64 * AS_STRIDE);              // [2][64]

    const int t = threadIdx.x;
    const int w = t >> 5, lane = t & 31;
    const int b = blockIdx.x >> 3;
    const int nt = blockIdx.x & 7;
    const int n0 = nt * 64;
    const int wrow = (w & 3) * 16;
    const int whalf = w >> 2;

    {
        const uint4* src =
            (const uint4*)(g_mh_split + ((size_t)(b * 512 + n0)) * 256);
        #pragma unroll
        for (int k = 0; k < 8; ++k) {
            int i4 = t + 256 * k;
            int row = i4 >> 5, c8 = i4 & 31;
            *(uint4*)(As + row * AS_STRIDE + c8 * 8) = src[i4];
        }
    }

    const float C1 = 0.08838834764831845f * 2.0f * 1.4426950408889634f;
    const float C2 = 10.0f * 1.4426950408889634f;

    const int nr0 = n0 + wrow + (lane >> 2);
    const int nr1 = nr0 + 8;
    const int nr0c = (nr0 < Nn) ? nr0 : 0;
    const int nr1c = (nr1 < Nn) ? nr1 : 0;
    float rs0 = 0.f, rs1 = 0.f;

    unsigned arowb = wrow + (lane & 15);
    unsigned acolb = (lane >> 4) * 8;
    unsigned browb = whalf * 32 + (lane & 15);

    for (int gt = 0; gt < 8; ++gt) {
        const int g0 = gt * 64;
        __syncthreads();
        {
            const uint4* src =
                (const uint4*)(g_enc_split + ((size_t)(b * 512 + g0)) * 256);
            #pragma unroll
            for (int k = 0; k < 8; ++k) {
                int i4 = t + 256 * k;
                int row = i4 >> 5, c8 = i4 & 31;
                *(uint4*)(Bs + row * AS_STRIDE + c8 * 8) = src[i4];
            }
        }
        __syncthreads();

        float acc[4][4];
        #pragma unroll
        for (int i = 0; i < 4; ++i)
            acc[i][0] = acc[i][1] = acc[i][2] = acc[i][3] = 0.f;

        #pragma unroll
        for (int kk = 0; kk < 8; ++kk) {
            unsigned aaddr = smem_u32(As + arowb * AS_STRIDE + acolb + kk * 16);
            unsigned ah[4], al[4];
            ldmx4(ah, aaddr);
            ldmx4(al, aaddr + 128 * 2);
            #pragma unroll
            for (int np = 0; np < 2; ++np) {
                unsigned baddr = smem_u32(Bs + (np * 16 + browb) * AS_STRIDE +
                                          acolb + kk * 16);
                unsigned bh[4], bl[4];
                ldmx4(bh, baddr);
                ldmx4(bl, baddr + 128 * 2);
                mma16816(acc[2 * np],     ah, bh[0], bh[2]);
                mma16816(acc[2 * np + 1], ah, bh[1], bh[3]);
                mma16816(acc[2 * np],     ah, bl[0], bl[2]);
                mma16816(acc[2 * np + 1], ah, bl[1], bl[3]);
                mma16816(acc[2 * np],     al, bh[0], bh[2]);
                mma16816(acc[2 * np + 1], al, bh[1], bh[3]);
            }
        }

        int mword = gt * 2 + whalf;
        unsigned w0 = g_maskbits[((size_t)b * Nn + nr0c) * 16 + mword];
        unsigned w1 = g_maskbits[((size_t)b * Nn + nr1c) * 16 + mword];

        #pragma unroll
        for (int ntile = 0; ntile < 4; ++ntile) {
            int bitb = ntile * 8 + (lane & 3) * 2;
            float p00, p01, p10, p11;
            {
                float u = exp2f(acc[ntile][0] * C1);
                p00 = exp2f(C2 * (1.0f - __fdividef(2.0f, u + 1.0f)));
            }
            {
                float u = exp2f(acc[ntile][1] * C1);
                p01 = exp2f(C2 * (1.0f - __fdividef(2.0f, u + 1.0f)));
            }
            {
                float u = exp2f(acc[ntile][2] * C1);
                p10 = exp2f(C2 * (1.0f - __fdividef(2.0f, u + 1.0f)));
            }
            {
                float u = exp2f(acc[ntile][3] * C1);
                p11 = exp2f(C2 * (1.0f - __fdividef(2.0f, u + 1.0f)));
            }
            p00 = ((w0 >> bitb) & 1u) ? p00 : 0.f;
            p01 = ((w0 >> (bitb + 1)) & 1u) ? p01 : 0.f;
            p10 = ((w1 >> bitb) & 1u) ? p10 : 0.f;
            p11 = ((w1 >> (bitb + 1)) & 1u) ? p11 : 0.f;
            rs0 += p00 + p01;
            rs1 += p10 + p11;
            int g = g0 + whalf * 32 + ntile * 8 + (lane & 3) * 2;
            if (g < Nn) {
                if (nr0 < Nn)
                    *(float2*)(out + ((size_t)b * Nn + nr0) * Nn + g) =
                        make_float2(p00, p01);
                if (nr1 < Nn)
                    *(float2*)(out + ((size_t)b * Nn + nr1) * Nn + g) =
                        make_float2(p10, p11);
            }
        }
    }

    rs0 += __shfl_xor_sync(0xffffffffu, rs0, 1);
    rs0 += __shfl_xor_sync(0xffffffffu, rs0, 2);
    rs1 += __shfl_xor_sync(0xffffffffu, rs1, 1);
    rs1 += __shfl_xor_sync(0xffffffffu, rs1, 2);
    if ((lane & 3) == 0) {
        rsum[whalf * 64 + wrow + (lane >> 2)] = rs0;
        rsum[whalf * 64 + wrow + (lane >> 2) + 8] = rs1;
    }
    __syncthreads();

    for (int i4 = t; i4 < 64 * 125; i4 += 256) {
        int row = i4 / 125, c4 = i4 - row * 125;
        int n = n0 + row;
        if (n < Nn) {
            float inv = __fdividef(1.0f, rsum[row] + rsum[64 + row]);
            float4* po = (float4*)(out + ((size_t)b * Nn + n) * Nn) + c4;
            float4 p = *po;
            p.x *= inv; p.y *= inv; p.z *= inv; p.w *= inv;
            *po = p;
        }
    }
}

// ---------------------------------------------------------------------------
// Launch
// ---------------------------------------------------------------------------
extern "C" void kernel_launch(void* const* d_in, const int* in_sizes, int n_in,
                              void* d_out, int out_size) {
    const float* enc_nodes = (const float*)d_in[0];
    const float* enc_first = (const float*)d_in[1];
    const float* enc_last  = (const float*)d_in[2];
    const float* mask      = (const float*)d_in[3];
    const float* Wq_first  = (const float*)d_in[4];
    const float* Wq_last   = (const float*)d_in[5];
    const float* Wk        = (const float*)d_in[6];
    const float* Wv        = (const float*)d_in[7];
    const float* Wc        = (const float*)d_in[8];
    const float* bc        = (const float*)d_in[9];
    float* out = (float*)d_out;

    static int configured = 0;
    if (!configured) {
        cudaFuncSetAttribute(qkv_prep_kernel,
            cudaFuncAttributeMaxDynamicSharedMemorySize, PRJ64_SMEM);
        cudaFuncSetAttribute(combine_mma_kernel,
            cudaFuncAttributeMaxDynamicSharedMemorySize, PRJ64_SMEM);
        cudaFuncSetAttribute(attn_mma_kernel,
            cudaFuncAttributeMaxDynamicSharedMemorySize, ATT_SMEM);
        cudaFuncSetAttribute(pointer_mma_kernel,
            cudaFuncAttributeMaxDynamicSharedMemorySize, PTR_SMEM);
        configured = 1;
    }

    // 1) qkv (inline fp32 splits) + enc split + maskbits, one launch
    qkv_prep_kernel<<<3314, 256, PRJ64_SMEM>>>(enc_nodes, enc_first, enc_last,
                                               mask, Wq_first, Wq_last,
                                               Wk, Wv);
    // 2) attention
    attn_mma_kernel<<<Bb * Hh * 4, 256, ATT_SMEM>>>();
    // 3) combine (Wc split inline)
    combine_mma_kernel<<<1000, 256, PRJ64_SMEM>>>(Wc, bc);
    // 4) pointer
    pointer_mma_kernel<<<Bb * 8, 256, PTR_SMEM>>>(out);

    (void)in_sizes; (void)n_in; (void)out_size;
}

// round 13
// speedup vs baseline: 1.0207x; 1.0048x over previous
#include <cuda_runtime.h>
#include <cuda_bf16.h>
#include <math.h>

// ---------------------------------------------------------------------------
// POMO decoder v13 — v12 base; pointer re-tiled for occ 4 = single wave
// (512 blocks resident at once). B=64, N=500, E=128, H=8, D=16
// ---------------------------------------------------------------------------

#define Bb 64
#define Nn 500
#define Hh 8
#define QKV_STRIDE 40

typedef unsigned long long ull;

__device__ unsigned g_maskbits[Bb * Nn * 16];
__device__ __nv_bfloat16 g_q_split[Bb * Hh * 512 * QKV_STRIDE];
__device__ __nv_bfloat16 g_k_split[Bb * Hh * 512 * QKV_STRIDE];
__device__ __nv_bfloat16 g_v_split[Bb * Hh * 512 * QKV_STRIDE];
__device__ __nv_bfloat16 g_enc_split[Bb * 512 * 256];
__device__ __nv_bfloat16 g_att_split[Bb * 512 * 256];
__device__ __nv_bfloat16 g_mh_split[Bb * 512 * 256];

__device__ __forceinline__ unsigned smem_u32(const void* p) {
    unsigned a;
    asm("{ .reg .u64 t; cvta.to.shared.u64 t, %1; cvt.u32.u64 %0, t; }"
        : "=r"(a) : "l"(p));
    return a;
}

__device__ __forceinline__ void ldmx4(unsigned* r, unsigned addr) {
    asm volatile(
        "ldmatrix.sync.aligned.m8n8.x4.shared.b16 {%0,%1,%2,%3}, [%4];"
        : "=r"(r[0]), "=r"(r[1]), "=r"(r[2]), "=r"(r[3]) : "r"(addr));
}
__device__ __forceinline__ void ldmx4t(unsigned* r, unsigned addr) {
    asm volatile(
        "ldmatrix.sync.aligned.m8n8.x4.trans.shared.b16 {%0,%1,%2,%3}, [%4];"
        : "=r"(r[0]), "=r"(r[1]), "=r"(r[2]), "=r"(r[3]) : "r"(addr));
}
__device__ __forceinline__ void mma16816(float* c, const unsigned* a,
                                         unsigned b0, unsigned b1) {
    asm volatile(
        "mma.sync.aligned.m16n8k16.row.col.f32.bf16.bf16.f32 "
        "{%0,%1,%2,%3}, {%4,%5,%6,%7}, {%8,%9}, {%0,%1,%2,%3};"
        : "+f"(c[0]), "+f"(c[1]), "+f"(c[2]), "+f"(c[3])
        : "r"(a[0]), "r"(a[1]), "r"(a[2]), "r"(a[3]), "r"(b0), "r"(b1));
}
__device__ __forceinline__ unsigned pack_bf2(float x, float y) {
    __nv_bfloat162 h = __floats2bfloat162_rn(x, y);
    return *(unsigned*)&h;
}

// split one float4 into hi/lo bf16x2 pairs and store at smem row layout
__device__ __forceinline__ void split_store(__nv_bfloat16* d, float4 v) {
    __nv_bfloat162 h01 = __floats2bfloat162_rn(v.x, v.y);
    __nv_bfloat162 h23 = __floats2bfloat162_rn(v.z, v.w);
    float2 f01 = __bfloat1622float2(h01);
    float2 f23 = __bfloat1622float2(h23);
    __nv_bfloat162 l01 = __floats2bfloat162_rn(v.x - f01.x, v.y - f01.y);
    __nv_bfloat162 l23 = __floats2bfloat162_rn(v.z - f23.x, v.w - f23.y);
    *(__nv_bfloat162*)(d) = h01;
    *(__nv_bfloat162*)(d + 2) = h23;
    *(__nv_bfloat162*)(d + 128) = l01;
    *(__nv_bfloat162*)(d + 130) = l23;
}

// ---------------------------------------------------------------------------
// HMMA 64x64 projection core (v12)
// ---------------------------------------------------------------------------
#define PRJ64_SMEM ((64 + 64) * 264 * 2)

template <bool A_FP32>
__device__ __forceinline__ void proj64_body(
    const void* __restrict__ A0v, const float* __restrict__ W0,
    const void* __restrict__ A1v, const float* __restrict__ W1,
    const float* __restrict__ bias, __nv_bfloat16* __restrict__ outb,
    float scale, int mode, int m0, int f0) {
    extern __shared__ char smem[];
    __nv_bfloat16* As = (__nv_bfloat16*)smem;   // [64][264]
    __nv_bfloat16* Ws = As + 64 * 264;          // [64][264]

    const int t = threadIdx.x;
    const int w = t >> 5, lane = t & 31;
    const int wrow = (w & 3) * 16;
    const int whalf = w >> 2;

    float acc[4][4];
    #pragma unroll
    for (int i = 0; i < 4; ++i)
        acc[i][0] = acc[i][1] = acc[i][2] = acc[i][3] = 0.f;

    const int npass = (A1v != nullptr) ? 2 : 1;
    for (int p = 0; p < npass; ++p) {
        const void* Ap = p ? A1v : A0v;
        const float* Wp = p ? W1 : W0;
        if (p) __syncthreads();
        #pragma unroll
        for (int k = 0; k < 8; ++k) {
            int i4 = t + 256 * k;
            int row = i4 >> 5, e4 = i4 & 31;
            if (A_FP32) {
                float4 v = ((const float4*)Ap)[(size_t)(m0 + row) * 32 + e4];
                split_store(As + row * 264 + e4 * 4, v);
            } else {
                int m = m0 + row;
                int bb = m / Nn, nn = m - bb * Nn;
                uint4 v = *((const uint4*)((const __nv_bfloat16*)Ap +
                            ((size_t)(bb * 512 + nn)) * 256) + e4);
                *(uint4*)(As + row * 264 + e4 * 8) = v;
            }
        }
        #pragma unroll
        for (int k = 0; k < 8; ++k) {
            int i4 = t + 256 * k;
            int row = i4 >> 5, e4 = i4 & 31;
            float4 v = ((const float4*)Wp)[(size_t)(f0 + row) * 32 + e4];
            split_store(Ws + row * 264 + e4 * 4, v);
        }
        __syncthreads();

        unsigned arowb = wrow + (lane & 15);
        unsigned acolb = (lane >> 4) * 8;
        unsigned browb = whalf * 32 + (lane & 15);
        #pragma unroll
        for (int kk = 0; kk < 8; ++kk) {
            unsigned aaddr = smem_u32(As + arowb * 264 + acolb + kk * 16);
            unsigned ah[4], al[4];
            ldmx4(ah, aaddr);
            ldmx4(al, aaddr + 128 * 2);
            #pragma unroll
            for (int np = 0; np < 2; ++np) {
                unsigned baddr = smem_u32(Ws + (np * 16 + browb) * 264 +
                                          acolb + kk * 16);
                unsigned bh[4], bl[4];
                ldmx4(bh, baddr);
                ldmx4(bl, baddr + 128 * 2);
                mma16816(acc[2 * np],     ah, bh[0], bh[2]);
                mma16816(acc[2 * np + 1], ah, bh[1], bh[3]);
                mma16816(acc[2 * np],     ah, bl[0], bl[2]);
                mma16816(acc[2 * np + 1], ah, bl[1], bl[3]);
                mma16816(acc[2 * np],     al, bh[0], bh[2]);
                mma16816(acc[2 * np + 1], al, bh[1], bh[3]);
            }
        }
        if (p + 1 < npass) __syncthreads();
    }

    const int mr0 = m0 + wrow + (lane >> 2);
    const int mr1 = mr0 + 8;
    const int b0 = mr0 / Nn, n0v = mr0 - b0 * Nn;
    const int b1 = mr1 / Nn, n1v = mr1 - b1 * Nn;
    #pragma unroll
    for (int ntile = 0; ntile < 4; ++ntile) {
        int f = f0 + whalf * 32 + ntile * 8 + (lane & 3) * 2;
        float bb0 = 0.f, bb1 = 0.f;
        if (bias) { bb0 = bias[f]; bb1 = bias[f + 1]; }
        float r00 = (acc[ntile][0] + bb0) * scale;
        float r01 = (acc[ntile][1] + bb1) * scale;
        float r10 = (acc[ntile][2] + bb0) * scale;
        float r11 = (acc[ntile][3] + bb1) * scale;
        __nv_bfloat162 h0 = __floats2bfloat162_rn(r00, r01);
        float2 ff0 = __bfloat1622float2(h0);
        unsigned lo0 = pack_bf2(r00 - ff0.x, r01 - ff0.y);
        __nv_bfloat162 h1 = __floats2bfloat162_rn(r10, r11);
        float2 ff1 = __bfloat1622float2(h1);
        unsigned lo1 = pack_bf2(r10 - ff1.x, r11 - ff1.y);
        if (mode == 0) {
            int h = f >> 4, d = f & 15;
            size_t base0 =
                ((size_t)((b0 * Hh + h) * 512 + n0v)) * QKV_STRIDE + d;
            *(unsigned*)(outb + base0) = *(unsigned*)&h0;
            *(unsigned*)(outb + base0 + 16) = lo0;
            size_t base1 =
                ((size_t)((b1 * Hh + h) * 512 + n1v)) * QKV_STRIDE + d;
            *(unsigned*)(outb + base1) = *(unsigned*)&h1;
            *(unsigned*)(outb + base1 + 16) = lo1;
        } else {
            size_t base0 = ((size_t)(b0 * 512 + n0v)) * 256 + f;
            *(unsigned*)(outb + base0) = *(unsigned*)&h0;
            *(unsigned*)(outb + base0 + 128) = lo0;
            size_t base1 = ((size_t)(b1 * 512 + n1v)) * 256 + f;
            *(unsigned*)(outb + base1) = *(unsigned*)&h1;
            *(unsigned*)(outb + base1 + 128) = lo1;
        }
    }
}

// ---------------------------------------------------------------------------
// Launch 1: qkv projections (inline fp32 splits) + enc split + maskbits.
// ---------------------------------------------------------------------------
__global__ void __launch_bounds__(256, 3)
qkv_prep_kernel(const float* __restrict__ enc_nodes,
                const float* __restrict__ enc_first,
                const float* __restrict__ enc_last,
                const float* __restrict__ mask,
                const float* __restrict__ Wqf, const float* __restrict__ Wql,
                const float* __restrict__ Wk, const float* __restrict__ Wv) {
    int bi = blockIdx.x;
    if (bi < 3000) {
        const float QS = 1.4426950408889634f * 0.25f;  // log2e / sqrt(D)
        int which = bi / 1000;
        int rem = bi - which * 1000;
        int m0 = (rem >> 1) * 64;
        int f0 = (rem & 1) * 64;
        if (which == 0)
            proj64_body<true>(enc_first, Wqf, enc_last, Wql, nullptr,
                              g_q_split, QS, 0, m0, f0);
        else if (which == 1)
            proj64_body<true>(enc_nodes, Wk, nullptr, nullptr, nullptr,
                              g_k_split, 1.0f, 0, m0, f0);
        else
            proj64_body<true>(enc_nodes, Wv, nullptr, nullptr, nullptr,
                              g_v_split, 1.0f, 0, m0, f0);
    } else if (bi < 3064) {
        int b = bi - 3000;
        int t = threadIdx.x;
        const float4* src = (const float4*)(enc_nodes + (size_t)b * Nn * 128);
        for (int i4 = t; i4 < Nn * 32; i4 += 256) {
            int n = i4 >> 5, e4 = i4 & 31;
            split_store(g_enc_split + ((size_t)(b * 512 + n)) * 256 + e4 * 4,
                        src[i4]);
        }
    } else {
        int t = threadIdx.x;
        int wid = t >> 5, lane = t & 31;
        int rowbase = (bi - 3064) * 128 + wid * 16;
        for (int rr = 0; rr < 16; ++rr) {
            int row = rowbase + rr;
            const float* mrow = mask + (size_t)row * Nn;
            unsigned* brow = g_maskbits + (size_t)row * 16;
            #pragma unroll
            for (int w = 0; w < 16; ++w) {
                int g = w * 32 + lane;
                float v = (g < Nn) ? mrow[g] : -1e9f;
                unsigned bal = __ballot_sync(0xffffffffu, v > -1.0f);
                if (lane == 0) brow[w] = bal;
            }
        }
    }
}

// ---------------------------------------------------------------------------
// Launch 3: combine (A = att_split bf16, W = Wc fp32 inline split)
// ---------------------------------------------------------------------------
__global__ void __launch_bounds__(256, 3)
combine_mma_kernel(const float* __restrict__ Wc, const float* __restrict__ bc) {
    int bi = blockIdx.x;
    proj64_body<false>(g_att_split, Wc, nullptr, nullptr, bc,
                       g_mh_split, 1.0f, 1, (bi >> 1) * 64, (bi & 1) * 64);
}

// ---------------------------------------------------------------------------
// Launch 2: attention via HMMA (v12, best measured)
// ---------------------------------------------------------------------------
#define ATT_SMEM ((128 + 512 + 512) * QKV_STRIDE * 2)

__global__ void __launch_bounds__(256, 2)
attn_mma_kernel() {
    extern __shared__ char smem[];
    __nv_bfloat16* Qs = (__nv_bfloat16*)smem;
    __nv_bfloat16* Ks = Qs + 128 * QKV_STRIDE;
    __nv_bfloat16* Vs = Ks + 512 * QKV_STRIDE;

    const int t = threadIdx.x;
    const int w = t >> 5, lane = t & 31;
    const int bi = blockIdx.x;
    const int bh = bi >> 2, qt = bi & 3;
    const int b = bh >> 3, h = bh & 7;
    const int q0 = qt * 128;

    {
        const uint4* qsrc =
            (const uint4*)(g_q_split + ((size_t)bh * 512 + q0) * QKV_STRIDE);
        #pragma unroll
        for (int k = 0; k < 3; ++k) {
            int i = t + 256 * k;
            if (i < 640) ((uint4*)Qs)[i] = qsrc[i];
        }
        const uint4* ksrc =
            (const uint4*)(g_k_split + (size_t)bh * 512 * QKV_STRIDE);
        #pragma unroll
        for (int k = 0; k < 10; ++k)
            ((uint4*)Ks)[t + 256 * k] = ksrc[t + 256 * k];
        const uint4* vsrc =
            (const uint4*)(g_v_split + (size_t)bh * 512 * QKV_STRIDE);
        #pragma unroll
        for (int k = 0; k < 10; ++k)
            ((uint4*)Vs)[t + 256 * k] = vsrc[t + 256 * k];
    }
    __syncthreads();

    unsigned aq_hi[4], aq_lo[4];
    {
        unsigned qaddr = smem_u32(Qs + (w * 16 + (lane & 15)) * QKV_STRIDE +
                                  (lane >> 4) * 8);
        ldmx4(aq_hi, qaddr);
        ldmx4(aq_lo, qaddr + 32);
    }

    float oacc[2][4];
    #pragma unroll
    for (int j = 0; j < 4; ++j) { oacc[0][j] = 0.f; oacc[1][j] = 0.f; }
    float rs0 = 0.f, rs1 = 0.f;

    const int nr0 = q0 + w * 16 + (lane >> 2);
    const int nr1 = nr0 + 8;
    const int nr0c = (nr0 < Nn) ? nr0 : 0;
    const int nr1c = (nr1 < Nn) ? nr1 : 0;

    for (int gt = 0; gt < 4; ++gt) {
        const int g0 = gt * 128;

        float sacc[16][4];
        #pragma unroll
        for (int i = 0; i < 16; ++i)
            sacc[i][0] = sacc[i][1] = sacc[i][2] = sacc[i][3] = 0.f;

        #pragma unroll
        for (int np = 0; np < 8; ++np) {
            unsigned ka = smem_u32(Ks + (g0 + np * 16 + (lane & 15)) *
                                            QKV_STRIDE +
                                   (lane >> 4) * 8);
            unsigned kh[4], kl[4];
            ldmx4(kh, ka);
            ldmx4(kl, ka + 32);
            mma16816(sacc[2 * np],     aq_hi, kh[0], kh[2]);
            mma16816(sacc[2 * np],     aq_hi, kl[0], kl[2]);
            mma16816(sacc[2 * np],     aq_lo, kh[0], kh[2]);
            mma16816(sacc[2 * np + 1], aq_hi, kh[1], kh[3]);
            mma16816(sacc[2 * np + 1], aq_hi, kl[1], kl[3]);
            mma16816(sacc[2 * np + 1], aq_lo, kh[1], kh[3]);
        }

        uint4 m0 = *(const uint4*)(g_maskbits + ((size_t)b * Nn + nr0c) * 16 +
                                   gt * 4);
        uint4 m1 = *(const uint4*)(g_maskbits + ((size_t)b * Nn + nr1c) * 16 +
                                   gt * 4);
        unsigned mw0[4] = {m0.x, m0.y, m0.z, m0.w};
        unsigned mw1[4] = {m1.x, m1.y, m1.z, m1.w};

        #pragma unroll
        for (int kk = 0; kk < 8; ++kk) {
            unsigned pf_hi[4], pf_lo[4];
            #pragma unroll
            for (int half = 0; half < 2; ++half) {
                int ntile = 2 * kk + half;
                unsigned w0 = mw0[ntile >> 2];
                unsigned w1 = mw1[ntile >> 2];
                int bitb = (ntile & 3) * 8 + (lane & 3) * 2;
                float p00 = exp2f(sacc[ntile][0]);
                float p01 = exp2f(sacc[ntile][1]);
                float p10 = exp2f(sacc[ntile][2]);
                float p11 = exp2f(sacc[ntile][3]);
                p00 = ((w0 >> bitb) & 1u) ? p00 : 0.f;
                p01 = ((w0 >> (bitb + 1)) & 1u) ? p01 : 0.f;
                p10 = ((w1 >> bitb) & 1u) ? p10 : 0.f;
                p11 = ((w1 >> (bitb + 1)) & 1u) ? p11 : 0.f;
                rs0 += p00 + p01;
                rs1 += p10 + p11;
                __nv_bfloat162 h0 = __floats2bfloat162_rn(p00, p01);
                __nv_bfloat162 h1 = __floats2bfloat162_rn(p10, p11);
                float2 hf0 = __bfloat1622float2(h0);
                float2 hf1 = __bfloat1622float2(h1);
                pf_hi[2 * half + 0] = *(unsigned*)&h0;
                pf_hi[2 * half + 1] = *(unsigned*)&h1;
                pf_lo[2 * half + 0] = pack_bf2(p00 - hf0.x, p01 - hf0.y);
                pf_lo[2 * half + 1] = pack_bf2(p10 - hf1.x, p11 - hf1.y);
            }
            unsigned va = smem_u32(Vs + (g0 + kk * 16 + (lane & 15)) *
                                            QKV_STRIDE +
                                   (lane >> 4) * 8);
            unsigned vh[4], vl[4];
            ldmx4t(vh, va);
            ldmx4t(vl, va + 32);
            mma16816(oacc[0], pf_hi, vh[0], vh[1]);
            mma16816(oacc[0], pf_hi, vl[0], vl[1]);
            mma16816(oacc[0], pf_lo, vh[0], vh[1]);
            mma16816(oacc[1], pf_hi, vh[2], vh[3]);
            mma16816(oacc[1], pf_hi, vl[2], vl[3]);
            mma16816(oacc[1], pf_lo, vh[2], vh[3]);
        }
    }

    rs0 += __shfl_xor_sync(0xffffffffu, rs0, 1);
    rs0 += __shfl_xor_sync(0xffffffffu, rs0, 2);
    rs1 += __shfl_xor_sync(0xffffffffu, rs1, 1);
    rs1 += __shfl_xor_sync(0xffffffffu, rs1, 2);
    float inv0 = __fdividef(1.0f, rs0);
    float inv1 = __fdividef(1.0f, rs1);

    const int d0 = (lane & 3) * 2;
    if (nr0 < Nn) {
        size_t base = ((size_t)(b * 512 + nr0)) * 256 + h * 16 + d0;
        float v0 = oacc[0][0] * inv0, v1 = oacc[0][1] * inv0;
        __nv_bfloat162 hh = __floats2bfloat162_rn(v0, v1);
        float2 hf = __bfloat1622float2(hh);
        *(unsigned*)(g_att_split + base) = *(unsigned*)&hh;
        *(unsigned*)(g_att_split + base + 128) =
            pack_bf2(v0 - hf.x, v1 - hf.y);
        v0 = oacc[1][0] * inv0; v1 = oacc[1][1] * inv0;
        hh = __floats2bfloat162_rn(v0, v1);
        hf = __bfloat1622float2(hh);
        *(unsigned*)(g_att_split + base + 8) = *(unsigned*)&hh;
        *(unsigned*)(g_att_split + base + 8 + 128) =
            pack_bf2(v0 - hf.x, v1 - hf.y);
    }
    if (nr1 < Nn) {
        size_t base = ((size_t)(b * 512 + nr1)) * 256 + h * 16 + d0;
        float v0 = oacc[0][2] * inv1, v1 = oacc[0][3] * inv1;
        __nv_bfloat162 hh = __floats2bfloat162_rn(v0, v1);
        float2 hf = __bfloat1622float2(hh);
        *(unsigned*)(g_att_split + base) = *(unsigned*)&hh;
        *(unsigned*)(g_att_split + base + 128) =
            pack_bf2(v0 - hf.x, v1 - hf.y);
        v0 = oacc[1][2] * inv1; v1 = oacc[1][3] * inv1;
        hh = __floats2bfloat162_rn(v0, v1);
        hf = __bfloat1622float2(hh);
        *(unsigned*)(g_att_split + base + 8) = *(unsigned*)&hh;
        *(unsigned*)(g_att_split + base + 8 + 128) =
            pack_bf2(v0 - hf.x, v1 - hf.y);
    }
}

// ---------------------------------------------------------------------------
// Launch 4: pointer via HMMA v13 — occ 4, single wave (512 blocks resident).
// Block = (b, 64-row tile). 8 warps = 4 row stripes x 2 col groups (16 g).
// Inner: 16 g-tiles of 32. smem: As 64x264 + Bs 32x264 + rsum = 51200 B.
// ---------------------------------------------------------------------------
#define AS_STRIDE 264
#define PTR_SMEM ((64 + 32) * AS_STRIDE * 2 + 512)

__global__ void __launch_bounds__(256, 4)
pointer_mma_kernel(float* __restrict__ out) {
    extern __shared__ char smem[];
    __nv_bfloat16* As = (__nv_bfloat16*)smem;                 // [64][264]
    __nv_bfloat16* Bs = As + 64 * AS_STRIDE;                  // [32][264]
    float* rsum = (float*)(Bs + 32 * AS_STRIDE);              // [2][64]

    const int t = threadIdx.x;
    const int w = t >> 5, lane = t & 31;
    const int b = blockIdx.x >> 3;
    const int nt = blockIdx.x & 7;
    const int n0 = nt * 64;
    const int wrow = (w & 3) * 16;   // row stripe
    const int wcg = w >> 2;          // col group (16 g)

    {
        const uint4* src =
            (const uint4*)(g_mh_split + ((size_t)(b * 512 + n0)) * 256);
        #pragma unroll
        for (int k = 0; k < 8; ++k) {
            int i4 = t + 256 * k;
            int row = i4 >> 5, c8 = i4 & 31;
            *(uint4*)(As + row * AS_STRIDE + c8 * 8) = src[i4];
        }
    }

    const float C1 = 0.08838834764831845f * 2.0f * 1.4426950408889634f;
    const float C2 = 10.0f * 1.4426950408889634f;

    const int nr0 = n0 + wrow + (lane >> 2);
    const int nr1 = nr0 + 8;
    const int nr0c = (nr0 < Nn) ? nr0 : 0;
    const int nr1c = (nr1 < Nn) ? nr1 : 0;
    float rs0 = 0.f, rs1 = 0.f;

    const unsigned arowb = wrow + (lane & 15);
    const unsigned acolb = (lane >> 4) * 8;
    const unsigned browb = wcg * 16 + (lane & 15);

    for (int gt = 0; gt < 16; ++gt) {
        const int g0 = gt * 32;
        __syncthreads();
        {
            const uint4* src =
                (const uint4*)(g_enc_split + ((size_t)(b * 512 + g0)) * 256);
            #pragma unroll
            for (int k = 0; k < 4; ++k) {
                int i4 = t + 256 * k;
                int row = i4 >> 5, c8 = i4 & 31;
                *(uint4*)(Bs + row * AS_STRIDE + c8 * 8) = src[i4];
            }
        }
        __syncthreads();

        float acc[2][4];
        #pragma unroll
        for (int i = 0; i < 2; ++i)
            acc[i][0] = acc[i][1] = acc[i][2] = acc[i][3] = 0.f;

        #pragma unroll
        for (int kk = 0; kk < 8; ++kk) {
            unsigned aaddr = smem_u32(As + arowb * AS_STRIDE + acolb + kk * 16);
            unsigned ah[4], al[4];
            ldmx4(ah, aaddr);
            ldmx4(al, aaddr + 128 * 2);
            unsigned baddr = smem_u32(Bs + browb * AS_STRIDE + acolb + kk * 16);
            unsigned bh[4], bl[4];
            ldmx4(bh, baddr);
            ldmx4(bl, baddr + 128 * 2);
            mma16816(acc[0], ah, bh[0], bh[2]);
            mma16816(acc[1], ah, bh[1], bh[3]);
            mma16816(acc[0], ah, bl[0], bl[2]);
            mma16816(acc[1], ah, bl[1], bl[3]);
            mma16816(acc[0], al, bh[0], bh[2]);
            mma16816(acc[1], al, bh[1], bh[3]);
        }

        // mask: one 32-bit word per row for this gt (32 g per word)
        unsigned w0 = g_maskbits[((size_t)b * Nn + nr0c) * 16 + gt];
        unsigned w1 = g_maskbits[((size_t)b * Nn + nr1c) * 16 + gt];

        #pragma unroll
        for (int ntile = 0; ntile < 2; ++ntile) {
            int bitb = wcg * 16 + ntile * 8 + (lane & 3) * 2;
            float p00, p01, p10, p11;
            {
                float u = exp2f(acc[ntile][0] * C1);
                p00 = exp2f(C2 * (1.0f - __fdividef(2.0f, u + 1.0f)));
            }
            {
                float u = exp2f(acc[ntile][1] * C1);
                p01 = exp2f(C2 * (1.0f - __fdividef(2.0f, u + 1.0f)));
            }
            {
                float u = exp2f(acc[ntile][2] * C1);
                p10 = exp2f(C2 * (1.0f - __fdividef(2.0f, u + 1.0f)));
            }
            {
                float u = exp2f(acc[ntile][3] * C1);
                p11 = exp2f(C2 * (1.0f - __fdividef(2.0f, u + 1.0f)));
            }
            p00 = ((w0 >> bitb) & 1u) ? p00 : 0.f;
            p01 = ((w0 >> (bitb + 1)) & 1u) ? p01 : 0.f;
            p10 = ((w1 >> bitb) & 1u) ? p10 : 0.f;
            p11 = ((w1 >> (bitb + 1)) & 1u) ? p11 : 0.f;
            rs0 += p00 + p01;
            rs1 += p10 + p11;
            int g = g0 + wcg * 16 + ntile * 8 + (lane & 3) * 2;
            if (g < Nn) {
                if (nr0 < Nn)
                    *(float2*)(out + ((size_t)b * Nn + nr0) * Nn + g) =
                        make_float2(p00, p01);
                if (nr1 < Nn)
                    *(float2*)(out + ((size_t)b * Nn + nr1) * Nn + g) =
                        make_float2(p10, p11);
            }
        }
    }

    rs0 += __shfl_xor_sync(0xffffffffu, rs0, 1);
    rs0 += __shfl_xor_sync(0xffffffffu, rs0, 2);
    rs1 += __shfl_xor_sync(0xffffffffu, rs1, 1);
    rs1 += __shfl_xor_sync(0xffffffffu, rs1, 2);
    if ((lane & 3) == 0) {
        rsum[wcg * 64 + wrow + (lane >> 2)] = rs0;
        rsum[wcg * 64 + wrow + (lane >> 2) + 8] = rs1;
    }
    __syncthreads();

    for (int i4 = t; i4 < 64 * 125; i4 += 256) {
        int row = i4 / 125, c4 = i4 - row * 125;
        int n = n0 + row;
        if (n < Nn) {
            float inv = __fdividef(1.0f, rsum[row] + rsum[64 + row]);
            float4* po = (float4*)(out + ((size_t)b * Nn + n) * Nn) + c4;
            float4 p = *po;
            p.x *= inv; p.y *= inv; p.z *= inv; p.w *= inv;
            *po = p;
        }
    }
}

// ---------------------------------------------------------------------------
// Launch
// ---------------------------------------------------------------------------
extern "C" void kernel_launch(void* const* d_in, const int* in_sizes, int n_in,
                              void* d_out, int out_size) {
    const float* enc_nodes = (const float*)d_in[0];
    const float* enc_first = (const float*)d_in[1];
    const float* enc_last  = (const float*)d_in[2];
    const float* mask      = (const float*)d_in[3];
    const float* Wq_first  = (const float*)d_in[4];
    const float* Wq_last   = (const float*)d_in[5];
    const float* Wk        = (const float*)d_in[6];
    const float* Wv        = (const float*)d_in[7];
    const float* Wc        = (const float*)d_in[8];
    const float* bc        = (const float*)d_in[9];
    float* out = (float*)d_out;

    static int configured = 0;
    if (!configured) {
        cudaFuncSetAttribute(qkv_prep_kernel,
            cudaFuncAttributeMaxDynamicSharedMemorySize, PRJ64_SMEM);
        cudaFuncSetAttribute(combine_mma_kernel,
            cudaFuncAttributeMaxDynamicSharedMemorySize, PRJ64_SMEM);
        cudaFuncSetAttribute(attn_mma_kernel,
            cudaFuncAttributeMaxDynamicSharedMemorySize, ATT_SMEM);
        cudaFuncSetAttribute(pointer_mma_kernel,
            cudaFuncAttributeMaxDynamicSharedMemorySize, PTR_SMEM);
        configured = 1;
    }

    // 1) qkv (inline fp32 splits) + enc split + maskbits
    qkv_prep_kernel<<<3314, 256, PRJ64_SMEM>>>(enc_nodes, enc_first, enc_last,
                                               mask, Wq_first, Wq_last,
                                               Wk, Wv);
    // 2) attention
    attn_mma_kernel<<<Bb * Hh * 4, 256, ATT_SMEM>>>();
    // 3) combine
    combine_mma_kernel<<<1000, 256, PRJ64_SMEM>>>(Wc, bc);
    // 4) pointer (single wave: 512 blocks @ occ 4)
    pointer_mma_kernel<<<Bb * 8, 256, PTR_SMEM>>>(out);

    (void)in_sizes; (void)n_in; (void)out_size;
}

// round 14
// speedup vs baseline: 1.0334x; 1.0124x over previous
#include <cuda_runtime.h>
#include <cuda_bf16.h>
#include <math.h>

// ---------------------------------------------------------------------------
// POMO decoder v14 — v13 base; pointer re-tiled: 128-row blocks, occ 2,
// single wave (256 blocks), LDSM:MMA=0.5, register-pipelined B loads.
// B=64, N=500, E=128, H=8, D=16
// ---------------------------------------------------------------------------

#define Bb 64
#define Nn 500
#define Hh 8
#define QKV_STRIDE 40

typedef unsigned long long ull;

__device__ unsigned g_maskbits[Bb * Nn * 16];
__device__ __nv_bfloat16 g_q_split[Bb * Hh * 512 * QKV_STRIDE];
__device__ __nv_bfloat16 g_k_split[Bb * Hh * 512 * QKV_STRIDE];
__device__ __nv_bfloat16 g_v_split[Bb * Hh * 512 * QKV_STRIDE];
__device__ __nv_bfloat16 g_enc_split[Bb * 512 * 256];
__device__ __nv_bfloat16 g_att_split[Bb * 512 * 256];
__device__ __nv_bfloat16 g_mh_split[Bb * 512 * 256];

__device__ __forceinline__ unsigned smem_u32(const void* p) {
    unsigned a;
    asm("{ .reg .u64 t; cvta.to.shared.u64 t, %1; cvt.u32.u64 %0, t; }"
        : "=r"(a) : "l"(p));
    return a;
}

__device__ __forceinline__ void ldmx4(unsigned* r, unsigned addr) {
    asm volatile(
        "ldmatrix.sync.aligned.m8n8.x4.shared.b16 {%0,%1,%2,%3}, [%4];"
        : "=r"(r[0]), "=r"(r[1]), "=r"(r[2]), "=r"(r[3]) : "r"(addr));
}
__device__ __forceinline__ void ldmx4t(unsigned* r, unsigned addr) {
    asm volatile(
        "ldmatrix.sync.aligned.m8n8.x4.trans.shared.b16 {%0,%1,%2,%3}, [%4];"
        : "=r"(r[0]), "=r"(r[1]), "=r"(r[2]), "=r"(r[3]) : "r"(addr));
}
__device__ __forceinline__ void mma16816(float* c, const unsigned* a,
                                         unsigned b0, unsigned b1) {
    asm volatile(
        "mma.sync.aligned.m16n8k16.row.col.f32.bf16.bf16.f32 "
        "{%0,%1,%2,%3}, {%4,%5,%6,%7}, {%8,%9}, {%0,%1,%2,%3};"
        : "+f"(c[0]), "+f"(c[1]), "+f"(c[2]), "+f"(c[3])
        : "r"(a[0]), "r"(a[1]), "r"(a[2]), "r"(a[3]), "r"(b0), "r"(b1));
}
__device__ __forceinline__ unsigned pack_bf2(float x, float y) {
    __nv_bfloat162 h = __floats2bfloat162_rn(x, y);
    return *(unsigned*)&h;
}

// split one float4 into hi/lo bf16x2 pairs and store at smem row layout
__device__ __forceinline__ void split_store(__nv_bfloat16* d, float4 v) {
    __nv_bfloat162 h01 = __floats2bfloat162_rn(v.x, v.y);
    __nv_bfloat162 h23 = __floats2bfloat162_rn(v.z, v.w);
    float2 f01 = __bfloat1622float2(h01);
    float2 f23 = __bfloat1622float2(h23);
    __nv_bfloat162 l01 = __floats2bfloat162_rn(v.x - f01.x, v.y - f01.y);
    __nv_bfloat162 l23 = __floats2bfloat162_rn(v.z - f23.x, v.w - f23.y);
    *(__nv_bfloat162*)(d) = h01;
    *(__nv_bfloat162*)(d + 2) = h23;
    *(__nv_bfloat162*)(d + 128) = l01;
    *(__nv_bfloat162*)(d + 130) = l23;
}

// ---------------------------------------------------------------------------
// HMMA 64x64 projection core (v12/v13)
// ---------------------------------------------------------------------------
#define PRJ64_SMEM ((64 + 64) * 264 * 2)

template <bool A_FP32>
__device__ __forceinline__ void proj64_body(
    const void* __restrict__ A0v, const float* __restrict__ W0,
    const void* __restrict__ A1v, const float* __restrict__ W1,
    const float* __restrict__ bias, __nv_bfloat16* __restrict__ outb,
    float scale, int mode, int m0, int f0) {
    extern __shared__ char smem[];
    __nv_bfloat16* As = (__nv_bfloat16*)smem;   // [64][264]
    __nv_bfloat16* Ws = As + 64 * 264;          // [64][264]

    const int t = threadIdx.x;
    const int w = t >> 5, lane = t & 31;
    const int wrow = (w & 3) * 16;
    const int whalf = w >> 2;

    float acc[4][4];
    #pragma unroll
    for (int i = 0; i < 4; ++i)
        acc[i][0] = acc[i][1] = acc[i][2] = acc[i][3] = 0.f;

    const int npass = (A1v != nullptr) ? 2 : 1;
    for (int p = 0; p < npass; ++p) {
        const void* Ap = p ? A1v : A0v;
        const float* Wp = p ? W1 : W0;
        if (p) __syncthreads();
        #pragma unroll
        for (int k = 0; k < 8; ++k) {
            int i4 = t + 256 * k;
            int row = i4 >> 5, e4 = i4 & 31;
            if (A_FP32) {
                float4 v = ((const float4*)Ap)[(size_t)(m0 + row) * 32 + e4];
                split_store(As + row * 264 + e4 * 4, v);
            } else {
                int m = m0 + row;
                int bb = m / Nn, nn = m - bb * Nn;
                uint4 v = *((const uint4*)((const __nv_bfloat16*)Ap +
                            ((size_t)(bb * 512 + nn)) * 256) + e4);
                *(uint4*)(As + row * 264 + e4 * 8) = v;
            }
        }
        #pragma unroll
        for (int k = 0; k < 8; ++k) {
            int i4 = t + 256 * k;
            int row = i4 >> 5, e4 = i4 & 31;
            float4 v = ((const float4*)Wp)[(size_t)(f0 + row) * 32 + e4];
            split_store(Ws + row * 264 + e4 * 4, v);
        }
        __syncthreads();

        unsigned arowb = wrow + (lane & 15);
        unsigned acolb = (lane >> 4) * 8;
        unsigned browb = whalf * 32 + (lane & 15);
        #pragma unroll
        for (int kk = 0; kk < 8; ++kk) {
            unsigned aaddr = smem_u32(As + arowb * 264 + acolb + kk * 16);
            unsigned ah[4], al[4];
            ldmx4(ah, aaddr);
            ldmx4(al, aaddr + 128 * 2);
            #pragma unroll
            for (int np = 0; np < 2; ++np) {
                unsigned baddr = smem_u32(Ws + (np * 16 + browb) * 264 +
                                          acolb + kk * 16);
                unsigned bh[4], bl[4];
                ldmx4(bh, baddr);
                ldmx4(bl, baddr + 128 * 2);
                mma16816(acc[2 * np],     ah, bh[0], bh[2]);
                mma16816(acc[2 * np + 1], ah, bh[1], bh[3]);
                mma16816(acc[2 * np],     ah, bl[0], bl[2]);
                mma16816(acc[2 * np + 1], ah, bl[1], bl[3]);
                mma16816(acc[2 * np],     al, bh[0], bh[2]);
                mma16816(acc[2 * np + 1], al, bh[1], bh[3]);
            }
        }
        if (p + 1 < npass) __syncthreads();
    }

    const int mr0 = m0 + wrow + (lane >> 2);
    const int mr1 = mr0 + 8;
    const int b0 = mr0 / Nn, n0v = mr0 - b0 * Nn;
    const int b1 = mr1 / Nn, n1v = mr1 - b1 * Nn;
    #pragma unroll
    for (int ntile = 0; ntile < 4; ++ntile) {
        int f = f0 + whalf * 32 + ntile * 8 + (lane & 3) * 2;
        float bb0 = 0.f, bb1 = 0.f;
        if (bias) { bb0 = bias[f]; bb1 = bias[f + 1]; }
        float r00 = (acc[ntile][0] + bb0) * scale;
        float r01 = (acc[ntile][1] + bb1) * scale;
        float r10 = (acc[ntile][2] + bb0) * scale;
        float r11 = (acc[ntile][3] + bb1) * scale;
        __nv_bfloat162 h0 = __floats2bfloat162_rn(r00, r01);
        float2 ff0 = __bfloat1622float2(h0);
        unsigned lo0 = pack_bf2(r00 - ff0.x, r01 - ff0.y);
        __nv_bfloat162 h1 = __floats2bfloat162_rn(r10, r11);
        float2 ff1 = __bfloat1622float2(h1);
        unsigned lo1 = pack_bf2(r10 - ff1.x, r11 - ff1.y);
        if (mode == 0) {
            int h = f >> 4, d = f & 15;
            size_t base0 =
                ((size_t)((b0 * Hh + h) * 512 + n0v)) * QKV_STRIDE + d;
            *(unsigned*)(outb + base0) = *(unsigned*)&h0;
            *(unsigned*)(outb + base0 + 16) = lo0;
            size_t base1 =
                ((size_t)((b1 * Hh + h) * 512 + n1v)) * QKV_STRIDE + d;
            *(unsigned*)(outb + base1) = *(unsigned*)&h1;
            *(unsigned*)(outb + base1 + 16) = lo1;
        } else {
            size_t base0 = ((size_t)(b0 * 512 + n0v)) * 256 + f;
            *(unsigned*)(outb + base0) = *(unsigned*)&h0;
            *(unsigned*)(outb + base0 + 128) = lo0;
            size_t base1 = ((size_t)(b1 * 512 + n1v)) * 256 + f;
            *(unsigned*)(outb + base1) = *(unsigned*)&h1;
            *(unsigned*)(outb + base1 + 128) = lo1;
        }
    }
}

// ---------------------------------------------------------------------------
// Launch 1: qkv projections (inline fp32 splits) + enc split + maskbits.
// ---------------------------------------------------------------------------
__global__ void __launch_bounds__(256, 3)
qkv_prep_kernel(const float* __restrict__ enc_nodes,
                const float* __restrict__ enc_first,
                const float* __restrict__ enc_last,
                const float* __restrict__ mask,
                const float* __restrict__ Wqf, const float* __restrict__ Wql,
                const float* __restrict__ Wk, const float* __restrict__ Wv) {
    int bi = blockIdx.x;
    if (bi < 3000) {
        const float QS = 1.4426950408889634f * 0.25f;  // log2e / sqrt(D)
        int which = bi / 1000;
        int rem = bi - which * 1000;
        int m0 = (rem >> 1) * 64;
        int f0 = (rem & 1) * 64;
        if (which == 0)
            proj64_body<true>(enc_first, Wqf, enc_last, Wql, nullptr,
                              g_q_split, QS, 0, m0, f0);
        else if (which == 1)
            proj64_body<true>(enc_nodes, Wk, nullptr, nullptr, nullptr,
                              g_k_split, 1.0f, 0, m0, f0);
        else
            proj64_body<true>(enc_nodes, Wv, nullptr, nullptr, nullptr,
                              g_v_split, 1.0f, 0, m0, f0);
    } else if (bi < 3064) {
        int b = bi - 3000;
        int t = threadIdx.x;
        const float4* src = (const float4*)(enc_nodes + (size_t)b * Nn * 128);
        for (int i4 = t; i4 < Nn * 32; i4 += 256) {
            int n = i4 >> 5, e4 = i4 & 31;
            split_store(g_enc_split + ((size_t)(b * 512 + n)) * 256 + e4 * 4,
                        src[i4]);
        }
    } else {
        int t = threadIdx.x;
        int wid = t >> 5, lane = t & 31;
        int rowbase = (bi - 3064) * 128 + wid * 16;
        for (int rr = 0; rr < 16; ++rr) {
            int row = rowbase + rr;
            const float* mrow = mask + (size_t)row * Nn;
            unsigned* brow = g_maskbits + (size_t)row * 16;
            #pragma unroll
            for (int w = 0; w < 16; ++w) {
                int g = w * 32 + lane;
                float v = (g < Nn) ? mrow[g] : -1e9f;
                unsigned bal = __ballot_sync(0xffffffffu, v > -1.0f);
                if (lane == 0) brow[w] = bal;
            }
        }
    }
}

// ---------------------------------------------------------------------------
// Launch 3: combine (A = att_split bf16, W = Wc fp32 inline split)
// ---------------------------------------------------------------------------
__global__ void __launch_bounds__(256, 3)
combine_mma_kernel(const float* __restrict__ Wc, const float* __restrict__ bc) {
    int bi = blockIdx.x;
    proj64_body<false>(g_att_split, Wc, nullptr, nullptr, bc,
                       g_mh_split, 1.0f, 1, (bi >> 1) * 64, (bi & 1) * 64);
}

// ---------------------------------------------------------------------------
// Launch 2: attention via HMMA (v12/v13, best measured)
// ---------------------------------------------------------------------------
#define ATT_SMEM ((128 + 512 + 512) * QKV_STRIDE * 2)

__global__ void __launch_bounds__(256, 2)
attn_mma_kernel() {
    extern __shared__ char smem[];
    __nv_bfloat16* Qs = (__nv_bfloat16*)smem;
    __nv_bfloat16* Ks = Qs + 128 * QKV_STRIDE;
    __nv_bfloat16* Vs = Ks + 512 * QKV_STRIDE;

    const int t = threadIdx.x;
    const int w = t >> 5, lane = t & 31;
    const int bi = blockIdx.x;
    const int bh = bi >> 2, qt = bi & 3;
    const int b = bh >> 3, h = bh & 7;
    const int q0 = qt * 128;

    {
        const uint4* qsrc =
            (const uint4*)(g_q_split + ((size_t)bh * 512 + q0) * QKV_STRIDE);
        #pragma unroll
        for (int k = 0; k < 3; ++k) {
            int i = t + 256 * k;
            if (i < 640) ((uint4*)Qs)[i] = qsrc[i];
        }
        const uint4* ksrc =
            (const uint4*)(g_k_split + (size_t)bh * 512 * QKV_STRIDE);
        #pragma unroll
        for (int k = 0; k < 10; ++k)
            ((uint4*)Ks)[t + 256 * k] = ksrc[t + 256 * k];
        const uint4* vsrc =
            (const uint4*)(g_v_split + (size_t)bh * 512 * QKV_STRIDE);
        #pragma unroll
        for (int k = 0; k < 10; ++k)
            ((uint4*)Vs)[t + 256 * k] = vsrc[t + 256 * k];
    }
    __syncthreads();

    unsigned aq_hi[4], aq_lo[4];
    {
        unsigned qaddr = smem_u32(Qs + (w * 16 + (lane & 15)) * QKV_STRIDE +
                                  (lane >> 4) * 8);
        ldmx4(aq_hi, qaddr);
        ldmx4(aq_lo, qaddr + 32);
    }

    float oacc[2][4];
    #pragma unroll
    for (int j = 0; j < 4; ++j) { oacc[0][j] = 0.f; oacc[1][j] = 0.f; }
    float rs0 = 0.f, rs1 = 0.f;

    const int nr0 = q0 + w * 16 + (lane >> 2);
    const int nr1 = nr0 + 8;
    const int nr0c = (nr0 < Nn) ? nr0 : 0;
    const int nr1c = (nr1 < Nn) ? nr1 : 0;

    for (int gt = 0; gt < 4; ++gt) {
        const int g0 = gt * 128;

        float sacc[16][4];
        #pragma unroll
        for (int i = 0; i < 16; ++i)
            sacc[i][0] = sacc[i][1] = sacc[i][2] = sacc[i][3] = 0.f;

        #pragma unroll
        for (int np = 0; np < 8; ++np) {
            unsigned ka = smem_u32(Ks + (g0 + np * 16 + (lane & 15)) *
                                            QKV_STRIDE +
                                   (lane >> 4) * 8);
            unsigned kh[4], kl[4];
            ldmx4(kh, ka);
            ldmx4(kl, ka + 32);
            mma16816(sacc[2 * np],     aq_hi, kh[0], kh[2]);
            mma16816(sacc[2 * np],     aq_hi, kl[0], kl[2]);
            mma16816(sacc[2 * np],     aq_lo, kh[0], kh[2]);
            mma16816(sacc[2 * np + 1], aq_hi, kh[1], kh[3]);
            mma16816(sacc[2 * np + 1], aq_hi, kl[1], kl[3]);
            mma16816(sacc[2 * np + 1], aq_lo, kh[1], kh[3]);
        }

        uint4 m0 = *(const uint4*)(g_maskbits + ((size_t)b * Nn + nr0c) * 16 +
                                   gt * 4);
        uint4 m1 = *(const uint4*)(g_maskbits + ((size_t)b * Nn + nr1c) * 16 +
                                   gt * 4);
        unsigned mw0[4] = {m0.x, m0.y, m0.z, m0.w};
        unsigned mw1[4] = {m1.x, m1.y, m1.z, m1.w};

        #pragma unroll
        for (int kk = 0; kk < 8; ++kk) {
            unsigned pf_hi[4], pf_lo[4];
            #pragma unroll
            for (int half = 0; half < 2; ++half) {
                int ntile = 2 * kk + half;
                unsigned w0 = mw0[ntile >> 2];
                unsigned w1 = mw1[ntile >> 2];
                int bitb = (ntile & 3) * 8 + (lane & 3) * 2;
                float p00 = exp2f(sacc[ntile][0]);
                float p01 = exp2f(sacc[ntile][1]);
                float p10 = exp2f(sacc[ntile][2]);
                float p11 = exp2f(sacc[ntile][3]);
                p00 = ((w0 >> bitb) & 1u) ? p00 : 0.f;
                p01 = ((w0 >> (bitb + 1)) & 1u) ? p01 : 0.f;
                p10 = ((w1 >> bitb) & 1u) ? p10 : 0.f;
                p11 = ((w1 >> (bitb + 1)) & 1u) ? p11 : 0.f;
                rs0 += p00 + p01;
                rs1 += p10 + p11;
                __nv_bfloat162 h0 = __floats2bfloat162_rn(p00, p01);
                __nv_bfloat162 h1 = __floats2bfloat162_rn(p10, p11);
                float2 hf0 = __bfloat1622float2(h0);
                float2 hf1 = __bfloat1622float2(h1);
                pf_hi[2 * half + 0] = *(unsigned*)&h0;
                pf_hi[2 * half + 1] = *(unsigned*)&h1;
                pf_lo[2 * half + 0] = pack_bf2(p00 - hf0.x, p01 - hf0.y);
                pf_lo[2 * half + 1] = pack_bf2(p10 - hf1.x, p11 - hf1.y);
            }
            unsigned va = smem_u32(Vs + (g0 + kk * 16 + (lane & 15)) *
                                            QKV_STRIDE +
                                   (lane >> 4) * 8);
            unsigned vh[4], vl[4];
            ldmx4t(vh, va);
            ldmx4t(vl, va + 32);
            mma16816(oacc[0], pf_hi, vh[0], vh[1]);
            mma16816(oacc[0], pf_hi, vl[0], vl[1]);
            mma16816(oacc[0], pf_lo, vh[0], vh[1]);
            mma16816(oacc[1], pf_hi, vh[2], vh[3]);
            mma16816(oacc[1], pf_hi, vl[2], vl[3]);
            mma16816(oacc[1], pf_lo, vh[2], vh[3]);
        }
    }

    rs0 += __shfl_xor_sync(0xffffffffu, rs0, 1);
    rs0 += __shfl_xor_sync(0xffffffffu, rs0, 2);
    rs1 += __shfl_xor_sync(0xffffffffu, rs1, 1);
    rs1 += __shfl_xor_sync(0xffffffffu, rs1, 2);
    float inv0 = __fdividef(1.0f, rs0);
    float inv1 = __fdividef(1.0f, rs1);

    const int d0 = (lane & 3) * 2;
    if (nr0 < Nn) {
        size_t base = ((size_t)(b * 512 + nr0)) * 256 + h * 16 + d0;
        float v0 = oacc[0][0] * inv0, v1 = oacc[0][1] * inv0;
        __nv_bfloat162 hh = __floats2bfloat162_rn(v0, v1);
        float2 hf = __bfloat1622float2(hh);
        *(unsigned*)(g_att_split + base) = *(unsigned*)&hh;
        *(unsigned*)(g_att_split + base + 128) =
            pack_bf2(v0 - hf.x, v1 - hf.y);
        v0 = oacc[1][0] * inv0; v1 = oacc[1][1] * inv0;
        hh = __floats2bfloat162_rn(v0, v1);
        hf = __bfloat1622float2(hh);
        *(unsigned*)(g_att_split + base + 8) = *(unsigned*)&hh;
        *(unsigned*)(g_att_split + base + 8 + 128) =
            pack_bf2(v0 - hf.x, v1 - hf.y);
    }
    if (nr1 < Nn) {
        size_t base = ((size_t)(b * 512 + nr1)) * 256 + h * 16 + d0;
        float v0 = oacc[0][2] * inv1, v1 = oacc[0][3] * inv1;
        __nv_bfloat162 hh = __floats2bfloat162_rn(v0, v1);
        float2 hf = __bfloat1622float2(hh);
        *(unsigned*)(g_att_split + base) = *(unsigned*)&hh;
        *(unsigned*)(g_att_split + base + 128) =
            pack_bf2(v0 - hf.x, v1 - hf.y);
        v0 = oacc[1][2] * inv1; v1 = oacc[1][3] * inv1;
        hh = __floats2bfloat162_rn(v0, v1);
        hf = __bfloat1622float2(hh);
        *(unsigned*)(g_att_split + base + 8) = *(unsigned*)&hh;
        *(unsigned*)(g_att_split + base + 8 + 128) =
            pack_bf2(v0 - hf.x, v1 - hf.y);
    }
}

// ---------------------------------------------------------------------------
// Launch 4: pointer v14 — 128-row blocks, occ 2, single wave (256 blocks),
// warp = 16 rows x 32 g (LDSM:MMA = 0.5), register-pipelined B tiles.
// smem: As 128x264 + Bs 32x264 + rsum[128] = 84992 B.
// ---------------------------------------------------------------------------
#define AS_STRIDE 264
#define PTR_SMEM ((128 + 32) * AS_STRIDE * 2 + 512)

__global__ void __launch_bounds__(256, 2)
pointer_mma_kernel(float* __restrict__ out) {
    extern __shared__ char smem[];
    __nv_bfloat16* As = (__nv_bfloat16*)smem;                 // [128][264]
    __nv_bfloat16* Bs = As + 128 * AS_STRIDE;                 // [32][264]
    float* rsum = (float*)(Bs + 32 * AS_STRIDE);              // [128]

    const int t = threadIdx.x;
    const int w = t >> 5, lane = t & 31;
    const int b = blockIdx.x >> 2;
    const int nt = blockIdx.x & 3;
    const int n0 = nt * 128;
    const int wrow = w * 16;          // each warp owns a unique 16-row stripe

    // As fill: 128 rows of mh_split (rows >=500 are zero padding)
    {
        const uint4* src =
            (const uint4*)(g_mh_split + ((size_t)(b * 512 + n0)) * 256);
        #pragma unroll
        for (int k = 0; k < 16; ++k) {
            int i4 = t + 256 * k;
            int row = i4 >> 5, c8 = i4 & 31;
            *(uint4*)(As + row * AS_STRIDE + c8 * 8) = src[i4];
        }
    }

    const float C1 = 0.08838834764831845f * 2.0f * 1.4426950408889634f;
    const float C2 = 10.0f * 1.4426950408889634f;

    const int nr0 = n0 + wrow + (lane >> 2);
    const int nr1 = nr0 + 8;
    const int nr0c = (nr0 < Nn) ? nr0 : 0;
    const int nr1c = (nr1 < Nn) ? nr1 : 0;
    float rs0 = 0.f, rs1 = 0.f;

    const unsigned arowb = wrow + (lane & 15);
    const unsigned kcolb = (lane >> 4) * 8;

    // prefetch gt=0 B tile (32 rows x 32 uint4 = 1024 / 256 threads = 4 each)
    uint4 pf[4];
    {
        const uint4* src = (const uint4*)(g_enc_split + ((size_t)(b * 512)) *
                                          256);
        #pragma unroll
        for (int k = 0; k < 4; ++k) pf[k] = src[t + 256 * k];
    }

    for (int gt = 0; gt < 16; ++gt) {
        // store prefetched tile
        #pragma unroll
        for (int k = 0; k < 4; ++k) {
            int i4 = t + 256 * k;
            int row = i4 >> 5, c8 = i4 & 31;
            *(uint4*)(Bs + row * AS_STRIDE + c8 * 8) = pf[k];
        }
        __syncthreads();
        // issue next tile's loads (overlap with MMA below)
        if (gt < 15) {
            const uint4* src = (const uint4*)(g_enc_split +
                ((size_t)(b * 512 + (gt + 1) * 32)) * 256);
            #pragma unroll
            for (int k = 0; k < 4; ++k) pf[k] = src[t + 256 * k];
        }

        float acc[4][4];
        #pragma unroll
        for (int i = 0; i < 4; ++i)
            acc[i][0] = acc[i][1] = acc[i][2] = acc[i][3] = 0.f;

        #pragma unroll
        for (int kk = 0; kk < 8; ++kk) {
            unsigned aaddr = smem_u32(As + arowb * AS_STRIDE + kcolb +
                                      kk * 16);
            unsigned ah[4], al[4];
            ldmx4(ah, aaddr);
            ldmx4(al, aaddr + 128 * 2);
            #pragma unroll
            for (int n16 = 0; n16 < 2; ++n16) {
                unsigned baddr = smem_u32(Bs + (n16 * 16 + (lane & 15)) *
                                              AS_STRIDE + kcolb + kk * 16);
                unsigned bh[4], bl[4];
                ldmx4(bh, baddr);
                ldmx4(bl, baddr + 128 * 2);
                mma16816(acc[2 * n16],     ah, bh[0], bh[2]);
                mma16816(acc[2 * n16 + 1], ah, bh[1], bh[3]);
                mma16816(acc[2 * n16],     ah, bl[0], bl[2]);
                mma16816(acc[2 * n16 + 1], ah, bl[1], bl[3]);
                mma16816(acc[2 * n16],     al, bh[0], bh[2]);
                mma16816(acc[2 * n16 + 1], al, bh[1], bh[3]);
            }
        }

        const int g0 = gt * 32;
        unsigned w0 = g_maskbits[((size_t)b * Nn + nr0c) * 16 + gt];
        unsigned w1 = g_maskbits[((size_t)b * Nn + nr1c) * 16 + gt];

        #pragma unroll
        for (int j = 0; j < 4; ++j) {
            int bitb = j * 8 + (lane & 3) * 2;
            float p00, p01, p10, p11;
            {
                float u = exp2f(acc[j][0] * C1);
                p00 = exp2f(C2 * (1.0f - __fdividef(2.0f, u + 1.0f)));
            }
            {
                float u = exp2f(acc[j][1] * C1);
                p01 = exp2f(C2 * (1.0f - __fdividef(2.0f, u + 1.0f)));
            }
            {
                float u = exp2f(acc[j][2] * C1);
                p10 = exp2f(C2 * (1.0f - __fdividef(2.0f, u + 1.0f)));
            }
            {
                float u = exp2f(acc[j][3] * C1);
                p11 = exp2f(C2 * (1.0f - __fdividef(2.0f, u + 1.0f)));
            }
            p00 = ((w0 >> bitb) & 1u) ? p00 : 0.f;
            p01 = ((w0 >> (bitb + 1)) & 1u) ? p01 : 0.f;
            p10 = ((w1 >> bitb) & 1u) ? p10 : 0.f;
            p11 = ((w1 >> (bitb + 1)) & 1u) ? p11 : 0.f;
            rs0 += p00 + p01;
            rs1 += p10 + p11;
            int g = g0 + j * 8 + (lane & 3) * 2;
            if (g < Nn) {
                if (nr0 < Nn)
                    *(float2*)(out + ((size_t)b * Nn + nr0) * Nn + g) =
                        make_float2(p00, p01);
                if (nr1 < Nn)
                    *(float2*)(out + ((size_t)b * Nn + nr1) * Nn + g) =
                        make_float2(p10, p11);
            }
        }
        __syncthreads();   // Bs consumed; next STS may overwrite
    }

    // per-warp rowsums (each warp owns its rows across all g)
    rs0 += __shfl_xor_sync(0xffffffffu, rs0, 1);
    rs0 += __shfl_xor_sync(0xffffffffu, rs0, 2);
    rs1 += __shfl_xor_sync(0xffffffffu, rs1, 1);
    rs1 += __shfl_xor_sync(0xffffffffu, rs1, 2);
    if ((lane & 3) == 0) {
        rsum[wrow + (lane >> 2)] = rs0;
        rsum[wrow + (lane >> 2) + 8] = rs1;
    }
    __syncthreads();

    // rescale: 128 rows x 125 float4
    for (int i4 = t; i4 < 128 * 125; i4 += 256) {
        int row = i4 / 125, c4 = i4 - row * 125;
        int n = n0 + row;
        if (n < Nn) {
            float inv = __fdividef(1.0f, rsum[row]);
            float4* po = (float4*)(out + ((size_t)b * Nn + n) * Nn) + c4;
            float4 p = *po;
            p.x *= inv; p.y *= inv; p.z *= inv; p.w *= inv;
            *po = p;
        }
    }
}

// ---------------------------------------------------------------------------
// Launch
// ---------------------------------------------------------------------------
extern "C" void kernel_launch(void* const* d_in, const int* in_sizes, int n_in,
                              void* d_out, int out_size) {
    const float* enc_nodes = (const float*)d_in[0];
    const float* enc_first = (const float*)d_in[1];
    const float* enc_last  = (const float*)d_in[2];
    const float* mask      = (const float*)d_in[3];
    const float* Wq_first  = (const float*)d_in[4];
    const float* Wq_last   = (const float*)d_in[5];
    const float* Wk        = (const float*)d_in[6];
    const float* Wv        = (const float*)d_in[7];
    const float* Wc        = (const float*)d_in[8];
    const float* bc        = (const float*)d_in[9];
    float* out = (float*)d_out;

    static int configured = 0;
    if (!configured) {
        cudaFuncSetAttribute(qkv_prep_kernel,
            cudaFuncAttributeMaxDynamicSharedMemorySize, PRJ64_SMEM);
        cudaFuncSetAttribute(combine_mma_kernel,
            cudaFuncAttributeMaxDynamicSharedMemorySize, PRJ64_SMEM);
        cudaFuncSetAttribute(attn_mma_kernel,
            cudaFuncAttributeMaxDynamicSharedMemorySize, ATT_SMEM);
        cudaFuncSetAttribute(pointer_mma_kernel,
            cudaFuncAttributeMaxDynamicSharedMemorySize, PTR_SMEM);
        configured = 1;
    }

    // 1) qkv (inline fp32 splits) + enc split + maskbits
    qkv_prep_kernel<<<3314, 256, PRJ64_SMEM>>>(enc_nodes, enc_first, enc_last,
                                               mask, Wq_first, Wq_last,
                                               Wk, Wv);
    // 2) attention
    attn_mma_kernel<<<Bb * Hh * 4, 256, ATT_SMEM>>>();
    // 3) combine
    combine_mma_kernel<<<1000, 256, PRJ64_SMEM>>>(Wc, bc);
    // 4) pointer (256 blocks @ occ 2, single wave, pipelined)
    pointer_mma_kernel<<<Bb * 4, 256, PTR_SMEM>>>(out);

    (void)in_sizes; (void)n_in; (void)out_size;
}